// round 1
// baseline (speedup 1.0000x reference)
#include <cuda_runtime.h>
#include <math.h>

#define BB 8
#define NN 128
#define CC 256
#define ROWS_TOT (BB*NN)        /* 1024 */

// ---------------- scratch (static device arrays; no allocation) ----------------
__device__ float g_q[ROWS_TOT*CC];
__device__ float g_k[ROWS_TOT*CC];
__device__ float g_v[ROWS_TOT*CC];

// ---------------- K1: q, k, v projections ----------------
// q = mol @ Wq + bq ; k = prot @ Wk + bk ; v = mol @ Wv + bv
// CTA handles 16 rows of the flattened [1024 x 256] activation matrices.
__global__ __launch_bounds__(256) void qkv_kernel(
    const float* __restrict__ mol, const float* __restrict__ prot,
    const float* __restrict__ Wq, const float* __restrict__ bq,
    const float* __restrict__ Wk, const float* __restrict__ bk,
    const float* __restrict__ Wv, const float* __restrict__ bv)
{
    __shared__ float Am[16*CC];
    __shared__ float Ap[16*CC];
    int tid = threadIdx.x;
    int r0  = blockIdx.x * 16;

    for (int i = tid; i < 16*CC; i += 256) {
        int r = i >> 8, c = i & 255;
        Am[i] = mol [(r0 + r)*CC + c];
        Ap[i] = prot[(r0 + r)*CC + c];
    }
    __syncthreads();

    int c = tid;
    float aq[16], ak[16], av[16];
#pragma unroll
    for (int r = 0; r < 16; r++) { aq[r]=0.f; ak[r]=0.f; av[r]=0.f; }

    for (int k = 0; k < CC; k++) {
        float wq = Wq[k*CC + c];
        float wk = Wk[k*CC + c];
        float wv = Wv[k*CC + c];
#pragma unroll
        for (int r = 0; r < 16; r++) {
            float am = Am[r*CC + k];
            float ap = Ap[r*CC + k];
            aq[r] += am*wq;
            ak[r] += ap*wk;
            av[r] += am*wv;
        }
    }
    float bqv = bq[c], bkv = bk[c], bvv = bv[c];
#pragma unroll
    for (int r = 0; r < 16; r++) {
        g_q[(r0+r)*CC + c] = aq[r] + bqv;
        g_k[(r0+r)*CC + c] = ak[r] + bkv;
        g_v[(r0+r)*CC + c] = av[r] + bvv;
    }
}

// ---------------- K2: fused edge kernel, one CTA per (b,m) ----------------
// SMEM layout (floats):
//   attn : 128*256      = 32768
//   Wt   : 32*256       =  8192
//   At   : 32*33        =  1056
//   qs   : 256
//   nodes: 256
#define SM_WT    (128*256)
#define SM_AT    (SM_WT + 32*256)
#define SM_QS    (SM_AT + 32*33)
#define SM_NODE  (SM_QS + 256)
#define SM_TOT   (SM_NODE + 256)
#define SMEM_BYTES (SM_TOT * 4)

// GEMM over a 32-row chunk: acc[4][8] per thread, rows = tr*4+i, cols = tc + 32*j.
// A sourced from global (adjacency) with transpose staging into At[kk][r] (pad 33).
__device__ __forceinline__ void gemm_chunk_global(
    const float* __restrict__ Asrc, const float* __restrict__ W,
    float* At, float* Wt, float acc[4][8], int n0, int tid, int tr, int tc)
{
    for (int k0 = 0; k0 < CC; k0 += 32) {
        __syncthreads();
        for (int i = tid; i < 32*32; i += 256) {
            int kk = i & 31, r = i >> 5;
            At[kk*33 + r] = Asrc[(n0 + r)*CC + k0 + kk];
        }
        for (int i = tid; i < 32*CC; i += 256) {
            int kk = i >> 8, c2 = i & 255;
            Wt[i] = W[(k0 + kk)*CC + c2];
        }
        __syncthreads();
#pragma unroll
        for (int kk = 0; kk < 32; kk++) {
            float a0 = At[kk*33 + tr*4 + 0];
            float a1 = At[kk*33 + tr*4 + 1];
            float a2 = At[kk*33 + tr*4 + 2];
            float a3 = At[kk*33 + tr*4 + 3];
#pragma unroll
            for (int j = 0; j < 8; j++) {
                float bj = Wt[kk*256 + tc + 32*j];
                acc[0][j] += a0*bj;
                acc[1][j] += a1*bj;
                acc[2][j] += a2*bj;
                acc[3][j] += a3*bj;
            }
        }
    }
}

// GEMM over a 32-row chunk with A already in SMEM (attn tile, row-major [128][256]).
__device__ __forceinline__ void gemm_chunk_smemA(
    const float* attn, const float* __restrict__ W,
    float* Wt, float acc[4][8], int n0, int tid, int tr, int tc)
{
    for (int k0 = 0; k0 < CC; k0 += 32) {
        __syncthreads();
        for (int i = tid; i < 32*CC; i += 256) {
            int kk = i >> 8, c2 = i & 255;
            Wt[i] = W[(k0 + kk)*CC + c2];
        }
        __syncthreads();
#pragma unroll
        for (int kk = 0; kk < 32; kk++) {
            const float* arow = attn + (n0 + tr*4)*CC + k0 + kk;
            float a0 = arow[0*CC];
            float a1 = arow[1*CC];
            float a2 = arow[2*CC];
            float a3 = arow[3*CC];
#pragma unroll
            for (int j = 0; j < 8; j++) {
                float bj = Wt[kk*256 + tc + 32*j];
                acc[0][j] += a0*bj;
                acc[1][j] += a1*bj;
                acc[2][j] += a2*bj;
                acc[3][j] += a3*bj;
            }
        }
    }
}

extern __shared__ float smem[];

__global__ __launch_bounds__(256) void edge_kernel(
    const float* __restrict__ mol_adj, const float* __restrict__ prot_adj,
    const float* __restrict__ Wka,  const float* __restrict__ bka,
    const float* __restrict__ Wva,  const float* __restrict__ bva,
    const float* __restrict__ Woed, const float* __restrict__ boed,
    const float* __restrict__ Wond, const float* __restrict__ bond,
    float* __restrict__ out_node, float* __restrict__ out_edge)
{
    float* attn  = smem;
    float* Wt    = smem + SM_WT;
    float* At    = smem + SM_AT;
    float* qs    = smem + SM_QS;
    float* nodes = smem + SM_NODE;

    int tid = threadIdx.x;
    int bm  = blockIdx.x;           // (b*128 + m)
    int b   = bm >> 7;
    int tr  = tid >> 5;             // 0..7 (row group of 4)
    int tc  = tid & 31;             // 0..31 (col stripe)

    const float* Am_base = mol_adj  + (size_t)bm * NN * CC;
    const float* Ap_base = prot_adj + (size_t)bm * NN * CC;

    qs[tid] = g_q[bm*CC + tid];

    for (int nch = 0; nch < 4; nch++) {
        int n0 = nch * 32;
        float acc[4][8];

        // ---- Phase A: prot_e -> attn := prot_e + bka + 1 ----
#pragma unroll
        for (int i = 0; i < 4; i++)
#pragma unroll
            for (int j = 0; j < 8; j++) acc[i][j] = 0.f;

        gemm_chunk_global(Ap_base, Wka, At, Wt, acc, n0, tid, tr, tc);

        {
            float bkav[8];
#pragma unroll
            for (int j = 0; j < 8; j++) bkav[j] = bka[tc + 32*j];
#pragma unroll
            for (int i = 0; i < 4; i++) {
                int r = n0 + tr*4 + i;
#pragma unroll
                for (int j = 0; j < 8; j++) {
                    int c = tc + 32*j;
                    attn[r*CC + c] = acc[i][j] + bkav[j] + 1.0f;
                }
            }
        }

        // ---- Phase B: mol_e, combine into attn ----
#pragma unroll
        for (int i = 0; i < 4; i++)
#pragma unroll
            for (int j = 0; j < 8; j++) acc[i][j] = 0.f;

        gemm_chunk_global(Am_base, Wva, At, Wt, acc, n0, tid, tr, tc);

        {
            float bvav[8];
#pragma unroll
            for (int j = 0; j < 8; j++) bvav[j] = bva[tc + 32*j];
#pragma unroll
            for (int i = 0; i < 4; i++) {
                int r = n0 + tr*4 + i;
#pragma unroll
                for (int j = 0; j < 8; j++) {
                    int c  = tc + 32*j;
                    float me = acc[i][j] + bvav[j];
                    float kv = g_k[((b << 7) + r)*CC + c];
                    attn[r*CC + c] = attn[r*CC + c] * me * qs[c] * kv * 0.0625f;
                }
            }
        }

        // ---- Phase C: mol_adj_out chunk = attn_chunk @ Woed + boed ----
        // (syncthreads inside gemm_chunk_smemA orders attn writes vs cross-thread reads)
#pragma unroll
        for (int i = 0; i < 4; i++)
#pragma unroll
            for (int j = 0; j < 8; j++) acc[i][j] = 0.f;

        gemm_chunk_smemA(attn, Woed, Wt, acc, n0, tid, tr, tc);

        {
            float boedv[8];
#pragma unroll
            for (int j = 0; j < 8; j++) boedv[j] = boed[tc + 32*j];
#pragma unroll
            for (int i = 0; i < 4; i++) {
                int r = n0 + tr*4 + i;
#pragma unroll
                for (int j = 0; j < 8; j++) {
                    int c = tc + 32*j;
                    out_edge[((size_t)bm*NN + r)*CC + c] = acc[i][j] + boedv[j];
                }
            }
        }
    }

    __syncthreads();

    // ---- Softmax over n (per channel c = tid), fused node reduction ----
    {
        int c = tid;
        float mx = -1e30f;
        for (int n = 0; n < NN; n++)
            mx = fmaxf(mx, attn[n*CC + c]);
        float s = 0.f, nv = 0.f;
        for (int n = 0; n < NN; n++) {
            float e = expf(attn[n*CC + c] - mx);
            s  += e;
            nv += e * g_v[((b << 7) + n)*CC + c];
        }
        nodes[c] = nv / s;
    }
    __syncthreads();

    // ---- node @ Wond + bond ----
    {
        int c = tid;
        float acc = 0.f;
        for (int cc = 0; cc < CC; cc++)
            acc += nodes[cc] * Wond[cc*CC + c];
        out_node[bm*CC + c] = acc + bond[c];
    }
}

// ---------------- launch ----------------
extern "C" void kernel_launch(void* const* d_in, const int* in_sizes, int n_in,
                              void* d_out, int out_size)
{
    const float* mol_annot  = (const float*)d_in[0];
    const float* prot_annot = (const float*)d_in[1];
    const float* mol_adj    = (const float*)d_in[2];
    const float* prot_adj   = (const float*)d_in[3];
    const float* Wq   = (const float*)d_in[4];   const float* bq   = (const float*)d_in[5];
    const float* Wk   = (const float*)d_in[6];   const float* bk   = (const float*)d_in[7];
    const float* Wv   = (const float*)d_in[8];   const float* bv   = (const float*)d_in[9];
    const float* Wka  = (const float*)d_in[10];  const float* bka  = (const float*)d_in[11];
    const float* Wva  = (const float*)d_in[12];  const float* bva  = (const float*)d_in[13];
    const float* Wond = (const float*)d_in[14];  const float* bond = (const float*)d_in[15];
    const float* Woed = (const float*)d_in[16];  const float* boed = (const float*)d_in[17];

    float* out = (float*)d_out;
    const size_t ANNOT = (size_t)BB*NN*CC;          //   262144
    const size_t ADJ   = (size_t)BB*NN*NN*CC;       // 33554432
    float* out_node       = out;                    // mol_annot_out
    float* out_prot_annot = out + ANNOT;            // prot_annot passthrough
    float* out_edge       = out + 2*ANNOT;          // mol_adj_out
    float* out_prot_adj   = out + 2*ANNOT + ADJ;    // prot_adj passthrough

    cudaFuncSetAttribute(edge_kernel,
                         cudaFuncAttributeMaxDynamicSharedMemorySize, SMEM_BYTES);

    cudaMemcpyAsync(out_prot_annot, prot_annot, ANNOT*sizeof(float),
                    cudaMemcpyDeviceToDevice, 0);
    cudaMemcpyAsync(out_prot_adj, prot_adj, ADJ*sizeof(float),
                    cudaMemcpyDeviceToDevice, 0);

    qkv_kernel<<<64, 256>>>(mol_annot, prot_annot, Wq, bq, Wk, bk, Wv, bv);

    edge_kernel<<<ROWS_TOT, 256, SMEM_BYTES>>>(
        mol_adj, prot_adj, Wka, bka, Wva, bva, Woed, boed, Wond, bond,
        out_node, out_edge);
}

// round 3
// speedup vs baseline: 3.8242x; 3.8242x over previous
#include <cuda_runtime.h>
#include <cuda_bf16.h>
#include <stdint.h>
#include <math.h>

#define BB 8
#define NN 128
#define CC 256
#define ROWS_TOT (BB*NN)     /* 1024 */

// ---------------- scratch (static device arrays; no allocation) ----------------
__device__ float g_q[ROWS_TOT*CC];      // [bm][c]
__device__ float g_kT[CC*ROWS_TOT];     // [c][bm]
__device__ float g_v[ROWS_TOT*CC];      // [bm][c]
__device__ __align__(16) __nv_bfloat16 g_WkaT_hi[CC*CC];   // W^T split: [n][k]
__device__ __align__(16) __nv_bfloat16 g_WkaT_lo[CC*CC];
__device__ __align__(16) __nv_bfloat16 g_WvaT_hi[CC*CC];
__device__ __align__(16) __nv_bfloat16 g_WvaT_lo[CC*CC];
__device__ __align__(16) __nv_bfloat16 g_WoedT_hi[CC*CC];
__device__ __align__(16) __nv_bfloat16 g_WoedT_lo[CC*CC];

// ---------------- helpers ----------------
__device__ __forceinline__ void mma_bf16(float acc[4],
    uint32_t a0, uint32_t a1, uint32_t a2, uint32_t a3,
    uint32_t b0, uint32_t b1)
{
    asm volatile(
        "mma.sync.aligned.m16n8k16.row.col.f32.bf16.bf16.f32 "
        "{%0,%1,%2,%3}, {%4,%5,%6,%7}, {%8,%9}, {%0,%1,%2,%3};"
        : "+f"(acc[0]), "+f"(acc[1]), "+f"(acc[2]), "+f"(acc[3])
        : "r"(a0), "r"(a1), "r"(a2), "r"(a3), "r"(b0), "r"(b1));
}

__device__ __forceinline__ void split2(float a, float b, uint32_t& hi, uint32_t& lo) {
    __nv_bfloat16 ha = __float2bfloat16(a), hb = __float2bfloat16(b);
    __nv_bfloat162 h; h.x = ha; h.y = hb;
    hi = *reinterpret_cast<uint32_t*>(&h);
    __nv_bfloat162 l;
    l.x = __float2bfloat16(a - __bfloat162float(ha));
    l.y = __float2bfloat16(b - __bfloat162float(hb));
    lo = *reinterpret_cast<uint32_t*>(&l);
}

// XOR-swizzled staging layout: buffers are [rows][64 bf16] = [rows][32 b32-words],
// word w at row r lives at byte r*128 + ((w ^ ((r&7)<<2))<<2).
__device__ __forceinline__ uint32_t swz_off(int row, int w) {
    return (uint32_t)(row*128 + (((w ^ ((row & 7) << 2))) << 2));
}

// ---------------- SMEM layout (bytes) ----------------
#define OFF_QS    0                   /* 256 f32 = 1024 */
#define OFF_AHI   1024                /* 128x64 bf16 = 16384 */
#define OFF_ALO   17408
#define OFF_BHI   33792               /* 256x64 bf16 = 32768 */
#define OFF_BLO   66560
#define OFF_ATTN  99328               /* 128x257 f32 = 131584 */
#define ATTN_STR  257
#define SMEM_BYTES 230912

// ---------------- weight prep: transpose + bf16 hi/lo split ----------------
__global__ __launch_bounds__(256) void wprep_kernel(
    const float* __restrict__ Wka, const float* __restrict__ Wva,
    const float* __restrict__ Woed)
{
    int i = blockIdx.x * 256 + threadIdx.x;   // i = n*256 + k
    int n = i >> 8, k = i & 255;
    {
        float w = Wka[k*CC + n];
        __nv_bfloat16 h = __float2bfloat16(w);
        g_WkaT_hi[i] = h;
        g_WkaT_lo[i] = __float2bfloat16(w - __bfloat162float(h));
    }
    {
        float w = Wva[k*CC + n];
        __nv_bfloat16 h = __float2bfloat16(w);
        g_WvaT_hi[i] = h;
        g_WvaT_lo[i] = __float2bfloat16(w - __bfloat162float(h));
    }
    {
        float w = Woed[k*CC + n];
        __nv_bfloat16 h = __float2bfloat16(w);
        g_WoedT_hi[i] = h;
        g_WoedT_lo[i] = __float2bfloat16(w - __bfloat162float(h));
    }
}

// ---------------- qkv projections (SIMT, small) ----------------
__global__ __launch_bounds__(256) void qkv_kernel(
    const float* __restrict__ mol, const float* __restrict__ prot,
    const float* __restrict__ Wq, const float* __restrict__ bq,
    const float* __restrict__ Wk, const float* __restrict__ bk,
    const float* __restrict__ Wv, const float* __restrict__ bv)
{
    __shared__ float Am[16*CC];
    __shared__ float Ap[16*CC];
    int tid = threadIdx.x;
    int r0  = blockIdx.x * 16;

    for (int i = tid; i < 16*CC; i += 256) {
        int r = i >> 8, c = i & 255;
        Am[i] = mol [(r0 + r)*CC + c];
        Ap[i] = prot[(r0 + r)*CC + c];
    }
    __syncthreads();

    int c = tid;
    float aq[16], ak[16], av[16];
#pragma unroll
    for (int r = 0; r < 16; r++) { aq[r]=0.f; ak[r]=0.f; av[r]=0.f; }
    for (int k = 0; k < CC; k++) {
        float wq = Wq[k*CC + c], wk = Wk[k*CC + c], wv = Wv[k*CC + c];
#pragma unroll
        for (int r = 0; r < 16; r++) {
            float am = Am[r*CC + k], ap = Ap[r*CC + k];
            aq[r] += am*wq; ak[r] += ap*wk; av[r] += am*wv;
        }
    }
    float bqv = bq[c], bkv = bk[c], bvv = bv[c];
#pragma unroll
    for (int r = 0; r < 16; r++) {
        g_q [(r0+r)*CC + c]       = aq[r] + bqv;
        g_kT[c*ROWS_TOT + r0 + r] = ak[r] + bkv;
        g_v [(r0+r)*CC + c]       = av[r] + bvv;
    }
}

extern __shared__ char smem_raw[];

// ---------------- staging helpers (all 256 threads) ----------------
// Stage fp32 A source [128 x 256] chunk k0..k0+63 -> bf16 hi/lo swizzled buffers.
__device__ __forceinline__ void stage_A_f32(const char* sm, const float* __restrict__ Ag,
                                            int k0, int tid)
{
#pragma unroll
    for (int u = 0; u < 8; u++) {
        int idx = u*256 + tid;
        int row = idx >> 4, q4 = idx & 15;
        float4 f = *(const float4*)(Ag + row*CC + k0 + q4*4);
        uint32_t h01, l01, h23, l23;
        split2(f.x, f.y, h01, l01);
        split2(f.z, f.w, h23, l23);
        uint32_t boff = swz_off(row, q4*2);
        *(uint2*)(const_cast<char*>(sm) + OFF_AHI + boff) = make_uint2(h01, h23);
        *(uint2*)(const_cast<char*>(sm) + OFF_ALO + boff) = make_uint2(l01, l23);
    }
}
// Stage pre-split W^T bf16 [256 x 256] chunk k0..k0+63 -> swizzled buffers.
__device__ __forceinline__ void stage_B(const char* sm,
    const __nv_bfloat16* __restrict__ Whi, const __nv_bfloat16* __restrict__ Wlo,
    int k0, int tid)
{
#pragma unroll
    for (int u = 0; u < 8; u++) {
        int idx = u*256 + tid;
        int row = idx >> 3, q = idx & 7;
        uint32_t boff = swz_off(row, q*4);
        *(uint4*)(const_cast<char*>(sm) + OFF_BHI + boff) = *(const uint4*)(Whi + row*CC + k0 + q*8);
        *(uint4*)(const_cast<char*>(sm) + OFF_BLO + boff) = *(const uint4*)(Wlo + row*CC + k0 + q*8);
    }
}

// MMA over the staged K=64 chunk. acc[4][8][4], warp tile 64x64 at (R0, C0).
__device__ __forceinline__ void mma_chunk(const char* sm, float acc[4][8][4],
                                          int R0, int C0, int lane)
{
    const int lg = lane >> 2;        // group id 0..7
    const int lt = lane & 3;         // thread in group
#pragma unroll
    for (int kk = 0; kk < 4; kk++) {
        const int w0 = kk*8 + lt, w1 = w0 + 4;
        uint32_t ah[4][4], al[4][4];
#pragma unroll
        for (int mt = 0; mt < 4; mt++) {
            int r0 = R0 + mt*16 + lg, r1 = r0 + 8;
            uint32_t o00 = swz_off(r0, w0), o10 = swz_off(r1, w0);
            uint32_t o01 = swz_off(r0, w1), o11 = swz_off(r1, w1);
            ah[mt][0] = *(const uint32_t*)(sm + OFF_AHI + o00);
            ah[mt][1] = *(const uint32_t*)(sm + OFF_AHI + o10);
            ah[mt][2] = *(const uint32_t*)(sm + OFF_AHI + o01);
            ah[mt][3] = *(const uint32_t*)(sm + OFF_AHI + o11);
            al[mt][0] = *(const uint32_t*)(sm + OFF_ALO + o00);
            al[mt][1] = *(const uint32_t*)(sm + OFF_ALO + o10);
            al[mt][2] = *(const uint32_t*)(sm + OFF_ALO + o01);
            al[mt][3] = *(const uint32_t*)(sm + OFF_ALO + o11);
        }
#pragma unroll
        for (int nt = 0; nt < 8; nt++) {
            int n = C0 + nt*8 + lg;
            uint32_t ob0 = swz_off(n, w0), ob1 = swz_off(n, w1);
            uint32_t bh0 = *(const uint32_t*)(sm + OFF_BHI + ob0);
            uint32_t bh1 = *(const uint32_t*)(sm + OFF_BHI + ob1);
            uint32_t bl0 = *(const uint32_t*)(sm + OFF_BLO + ob0);
            uint32_t bl1 = *(const uint32_t*)(sm + OFF_BLO + ob1);
#pragma unroll
            for (int mt = 0; mt < 4; mt++) {
                mma_bf16(acc[mt][nt], ah[mt][0], ah[mt][1], ah[mt][2], ah[mt][3], bh0, bh1);
                mma_bf16(acc[mt][nt], ah[mt][0], ah[mt][1], ah[mt][2], ah[mt][3], bl0, bl1);
                mma_bf16(acc[mt][nt], al[mt][0], al[mt][1], al[mt][2], al[mt][3], bh0, bh1);
            }
        }
    }
}

// ---------------- fused edge kernel, one CTA per (b,m) ----------------
__global__ __launch_bounds__(256, 1) void edge_kernel(
    const float* __restrict__ mol_adj, const float* __restrict__ prot_adj,
    const float* __restrict__ bka,  const float* __restrict__ bva,
    const float* __restrict__ boed, const float* __restrict__ bond,
    const float* __restrict__ Wond,
    float* __restrict__ out_node, float* __restrict__ out_edge,
    float* __restrict__ out_prot_adj)
{
    char* sm = smem_raw;
    const int tid = threadIdx.x, wid = tid >> 5, lane = tid & 31;
    const int lg = lane >> 2, lt = lane & 3;
    const int bm = blockIdx.x, b = bm >> 7;
    const int warp_m = wid >> 2, warp_n = wid & 3;   // 2 x 4 warp grid
    const int R0 = warp_m*64, C0 = warp_n*64;

    float* qs   = (float*)(sm + OFF_QS);
    float* attn = (float*)(sm + OFF_ATTN);

    qs[tid] = g_q[bm*CC + tid];

    // prot_adj passthrough (overlaps with compute)
    {
        const float4* src = (const float4*)(prot_adj + (size_t)bm*NN*CC);
        float4* dst = (float4*)(out_prot_adj + (size_t)bm*NN*CC);
        for (int i = tid; i < NN*CC/4; i += 256) dst[i] = src[i];
    }

    float acc[4][8][4];

    // ======== Phase A: prot_e -> attn := pe + bka + 1 ========
#pragma unroll
    for (int mt = 0; mt < 4; mt++)
#pragma unroll
        for (int nt = 0; nt < 8; nt++)
#pragma unroll
            for (int i = 0; i < 4; i++) acc[mt][nt][i] = 0.f;

    {
        const float* Ag = prot_adj + (size_t)bm*NN*CC;
        for (int ch = 0; ch < 4; ch++) {
            __syncthreads();
            stage_A_f32(sm, Ag, ch*64, tid);
            stage_B(sm, g_WkaT_hi, g_WkaT_lo, ch*64, tid);
            __syncthreads();
            mma_chunk(sm, acc, R0, C0, lane);
        }
    }
#pragma unroll
    for (int mt = 0; mt < 4; mt++) {
        int r = R0 + mt*16 + lg;
#pragma unroll
        for (int nt = 0; nt < 8; nt++) {
            int c = C0 + nt*8 + lt*2;
            float b0v = __ldg(bka + c) + 1.0f, b1v = __ldg(bka + c + 1) + 1.0f;
            attn[r*ATTN_STR + c]       = acc[mt][nt][0] + b0v;
            attn[r*ATTN_STR + c + 1]   = acc[mt][nt][1] + b1v;
            attn[(r+8)*ATTN_STR + c]   = acc[mt][nt][2] + b0v;
            attn[(r+8)*ATTN_STR + c+1] = acc[mt][nt][3] + b1v;
        }
    }

    // ======== Phase B: mol_e, combine into attn ========
#pragma unroll
    for (int mt = 0; mt < 4; mt++)
#pragma unroll
        for (int nt = 0; nt < 8; nt++)
#pragma unroll
            for (int i = 0; i < 4; i++) acc[mt][nt][i] = 0.f;

    {
        const float* Ag = mol_adj + (size_t)bm*NN*CC;
        for (int ch = 0; ch < 4; ch++) {
            __syncthreads();
            stage_A_f32(sm, Ag, ch*64, tid);
            stage_B(sm, g_WvaT_hi, g_WvaT_lo, ch*64, tid);
            __syncthreads();
            mma_chunk(sm, acc, R0, C0, lane);
        }
    }
    {
        const int bbase = b << 7;
#pragma unroll
        for (int mt = 0; mt < 4; mt++) {
            int r = R0 + mt*16 + lg;
#pragma unroll
            for (int nt = 0; nt < 8; nt++) {
                int c = C0 + nt*8 + lt*2;
                float bv0 = __ldg(bva + c), bv1 = __ldg(bva + c + 1);
                float q0 = qs[c] * 0.0625f, q1 = qs[c+1] * 0.0625f;
                float k00 = g_kT[c*ROWS_TOT + bbase + r];
                float k01 = g_kT[(c+1)*ROWS_TOT + bbase + r];
                float k10 = g_kT[c*ROWS_TOT + bbase + r + 8];
                float k11 = g_kT[(c+1)*ROWS_TOT + bbase + r + 8];
                attn[r*ATTN_STR + c]       *= (acc[mt][nt][0] + bv0) * q0 * k00;
                attn[r*ATTN_STR + c + 1]   *= (acc[mt][nt][1] + bv1) * q1 * k01;
                attn[(r+8)*ATTN_STR + c]   *= (acc[mt][nt][2] + bv0) * q0 * k10;
                attn[(r+8)*ATTN_STR + c+1] *= (acc[mt][nt][3] + bv1) * q1 * k11;
            }
        }
    }

    // ======== Phase C: edge_out = attn @ Woed + boed ========
#pragma unroll
    for (int mt = 0; mt < 4; mt++)
#pragma unroll
        for (int nt = 0; nt < 8; nt++)
#pragma unroll
            for (int i = 0; i < 4; i++) acc[mt][nt][i] = 0.f;

    {
        const int row = tid & 127, hk = tid >> 7;
        for (int ch = 0; ch < 4; ch++) {
            const int k0 = ch*64;
            __syncthreads();
            // stage A from attn smem (fp32 -> bf16 hi/lo, swizzled)
#pragma unroll
            for (int jj = 0; jj < 8; jj++) {
                int kloc = hk*32 + jj*4;
                const float* ap = attn + row*ATTN_STR + k0 + kloc;
                uint32_t h01, l01, h23, l23;
                split2(ap[0], ap[1], h01, l01);
                split2(ap[2], ap[3], h23, l23);
                uint32_t boff = swz_off(row, kloc >> 1);
                *(uint2*)(sm + OFF_AHI + boff) = make_uint2(h01, h23);
                *(uint2*)(sm + OFF_ALO + boff) = make_uint2(l01, l23);
            }
            stage_B(sm, g_WoedT_hi, g_WoedT_lo, k0, tid);
            __syncthreads();
            mma_chunk(sm, acc, R0, C0, lane);
        }
    }
    // epilogue: direct float2 stores
#pragma unroll
    for (int mt = 0; mt < 4; mt++) {
        int r = R0 + mt*16 + lg;
#pragma unroll
        for (int nt = 0; nt < 8; nt++) {
            int c = C0 + nt*8 + lt*2;
            float b0v = __ldg(boed + c), b1v = __ldg(boed + c + 1);
            float2 o0 = make_float2(acc[mt][nt][0] + b0v, acc[mt][nt][1] + b1v);
            float2 o1 = make_float2(acc[mt][nt][2] + b0v, acc[mt][nt][3] + b1v);
            *(float2*)(out_edge + ((size_t)bm*NN + r)*CC + c)     = o0;
            *(float2*)(out_edge + ((size_t)bm*NN + r + 8)*CC + c) = o1;
        }
    }

    __syncthreads();   // staging buffers free; attn stable

    // ======== softmax over n (per channel) + node projection ========
    {
        const int c = tid;
        float mx = -1e30f;
        for (int n = 0; n < NN; n++) mx = fmaxf(mx, attn[n*ATTN_STR + c]);
        float s = 0.f, nv = 0.f;
        const float* vb = g_v + (size_t)(b << 7)*CC + c;
        for (int n = 0; n < NN; n++) {
            float e = __expf(attn[n*ATTN_STR + c] - mx);
            s += e;
            nv += e * vb[(size_t)n*CC];
        }
        float* nodes = (float*)(sm + OFF_AHI);
        nodes[c] = nv / s;
        __syncthreads();
        float acc2 = 0.f;
        for (int cc2 = 0; cc2 < CC; cc2++) acc2 += nodes[cc2] * Wond[cc2*CC + c];
        out_node[bm*CC + c] = acc2 + __ldg(bond + c);
    }
}

// ---------------- launch ----------------
extern "C" void kernel_launch(void* const* d_in, const int* in_sizes, int n_in,
                              void* d_out, int out_size)
{
    const float* mol_annot  = (const float*)d_in[0];
    const float* prot_annot = (const float*)d_in[1];
    const float* mol_adj    = (const float*)d_in[2];
    const float* prot_adj   = (const float*)d_in[3];
    const float* Wq   = (const float*)d_in[4];   const float* bq   = (const float*)d_in[5];
    const float* Wk   = (const float*)d_in[6];   const float* bk   = (const float*)d_in[7];
    const float* Wv   = (const float*)d_in[8];   const float* bv   = (const float*)d_in[9];
    const float* Wka  = (const float*)d_in[10];  const float* bka  = (const float*)d_in[11];
    const float* Wva  = (const float*)d_in[12];  const float* bva  = (const float*)d_in[13];
    const float* Wond = (const float*)d_in[14];  const float* bond = (const float*)d_in[15];
    const float* Woed = (const float*)d_in[16];  const float* boed = (const float*)d_in[17];

    float* out = (float*)d_out;
    const size_t ANNOT = (size_t)BB*NN*CC;          //   262144
    const size_t ADJ   = (size_t)BB*NN*NN*CC;       // 33554432
    float* out_node       = out;
    float* out_prot_annot = out + ANNOT;
    float* out_edge       = out + 2*ANNOT;
    float* out_prot_adj   = out + 2*ANNOT + ADJ;

    cudaFuncSetAttribute(edge_kernel,
                         cudaFuncAttributeMaxDynamicSharedMemorySize, SMEM_BYTES);

    cudaMemcpyAsync(out_prot_annot, prot_annot, ANNOT*sizeof(float),
                    cudaMemcpyDeviceToDevice, 0);

    wprep_kernel<<<256, 256>>>(Wka, Wva, Woed);
    qkv_kernel<<<64, 256>>>(mol_annot, prot_annot, Wq, bq, Wk, bk, Wv, bv);

    edge_kernel<<<ROWS_TOT, 256, SMEM_BYTES>>>(
        mol_adj, prot_adj, bka, bva, boed, bond, Wond,
        out_node, out_edge, out_prot_adj);
}

// round 4
// speedup vs baseline: 4.0903x; 1.0696x over previous
#include <cuda_runtime.h>
#include <cuda_bf16.h>
#include <stdint.h>
#include <math.h>

#define BB 8
#define NN 128
#define CC 256
#define ROWS_TOT (BB*NN)     /* 1024 */

// ---------------- scratch (static device arrays; no allocation) ----------------
__device__ float g_q[ROWS_TOT*CC];      // [bm][c]
__device__ float g_kT[CC*ROWS_TOT];     // [c][bm]
__device__ float g_v[ROWS_TOT*CC];      // [bm][c]
__device__ __align__(16) __nv_bfloat16 g_WkaT_hi[CC*CC];   // W^T split: [n][k]
__device__ __align__(16) __nv_bfloat16 g_WkaT_lo[CC*CC];
__device__ __align__(16) __nv_bfloat16 g_WvaT_hi[CC*CC];
__device__ __align__(16) __nv_bfloat16 g_WvaT_lo[CC*CC];
__device__ __align__(16) __nv_bfloat16 g_WoedT_hi[CC*CC];
__device__ __align__(16) __nv_bfloat16 g_WoedT_lo[CC*CC];

// ---------------- helpers ----------------
__device__ __forceinline__ void mma_bf16(float acc[4],
    uint32_t a0, uint32_t a1, uint32_t a2, uint32_t a3,
    uint32_t b0, uint32_t b1)
{
    asm volatile(
        "mma.sync.aligned.m16n8k16.row.col.f32.bf16.bf16.f32 "
        "{%0,%1,%2,%3}, {%4,%5,%6,%7}, {%8,%9}, {%0,%1,%2,%3};"
        : "+f"(acc[0]), "+f"(acc[1]), "+f"(acc[2]), "+f"(acc[3])
        : "r"(a0), "r"(a1), "r"(a2), "r"(a3), "r"(b0), "r"(b1));
}

__device__ __forceinline__ void split2(float a, float b, uint32_t& hi, uint32_t& lo) {
    __nv_bfloat16 ha = __float2bfloat16(a), hb = __float2bfloat16(b);
    __nv_bfloat162 h; h.x = ha; h.y = hb;
    hi = *reinterpret_cast<uint32_t*>(&h);
    __nv_bfloat162 l;
    l.x = __float2bfloat16(a - __bfloat162float(ha));
    l.y = __float2bfloat16(b - __bfloat162float(hb));
    lo = *reinterpret_cast<uint32_t*>(&l);
}

__device__ __forceinline__ uint32_t smem_to_u32(const void* p) {
    uint32_t a;
    asm("{ .reg .u64 t; cvta.to.shared.u64 t, %1; cvt.u32.u64 %0, t; }" : "=r"(a) : "l"(p));
    return a;
}

#define CP_ASYNC16(dst_u32, src_ptr) \
    asm volatile("cp.async.cg.shared.global [%0], [%1], 16;" \
        :: "r"(dst_u32), "l"(src_ptr) : "memory")
#define CP_COMMIT()  asm volatile("cp.async.commit_group;" ::: "memory")
#define CP_WAIT0()   asm volatile("cp.async.wait_group 0;" ::: "memory")

// XOR-swizzled staging: buffers [rows][64 bf16] = [rows][32 words],
// word w of row r at byte r*128 + ((w ^ ((r&7)<<2))<<2).
__device__ __forceinline__ uint32_t swz_off(int row, int w) {
    return (uint32_t)(row*128 + (((w ^ ((row & 7) << 2))) << 2));
}

// ---------------- SMEM layout (bytes) ----------------
#define OFF_QS    0                   /* 256 f32 */
#define OFF_AHI   1024                /* 128x64 bf16 = 16384 */
#define OFF_ALO   17408
#define OFF_BHI   33792               /* 256x64 bf16 = 32768 */
#define OFF_BLO   66560
#define OFF_ATTN  99328               /* 128x257 f32 */
#define ATTN_STR  257
#define SMEM_BYTES 230912

// ---------------- merged prep: weight split (blocks 0..255) + qkv (256..319) ----
__global__ __launch_bounds__(256) void prep_kernel(
    const float* __restrict__ Wka, const float* __restrict__ Wva,
    const float* __restrict__ Woed,
    const float* __restrict__ mol, const float* __restrict__ prot,
    const float* __restrict__ Wq, const float* __restrict__ bq,
    const float* __restrict__ Wk, const float* __restrict__ bk,
    const float* __restrict__ Wv, const float* __restrict__ bv)
{
    int tid = threadIdx.x;
    if (blockIdx.x < 256) {
        int i = blockIdx.x * 256 + tid;   // i = n*256 + k
        int n = i >> 8, k = i & 255;
        {
            float w = Wka[k*CC + n];
            __nv_bfloat16 h = __float2bfloat16(w);
            g_WkaT_hi[i] = h;
            g_WkaT_lo[i] = __float2bfloat16(w - __bfloat162float(h));
        }
        {
            float w = Wva[k*CC + n];
            __nv_bfloat16 h = __float2bfloat16(w);
            g_WvaT_hi[i] = h;
            g_WvaT_lo[i] = __float2bfloat16(w - __bfloat162float(h));
        }
        {
            float w = Woed[k*CC + n];
            __nv_bfloat16 h = __float2bfloat16(w);
            g_WoedT_hi[i] = h;
            g_WoedT_lo[i] = __float2bfloat16(w - __bfloat162float(h));
        }
    } else {
        __shared__ float Am[16*CC];
        __shared__ float Ap[16*CC];
        int r0 = (blockIdx.x - 256) * 16;
        for (int i = tid; i < 16*CC; i += 256) {
            int r = i >> 8, c = i & 255;
            Am[i] = mol [(r0 + r)*CC + c];
            Ap[i] = prot[(r0 + r)*CC + c];
        }
        __syncthreads();
        int c = tid;
        float aq[16], ak[16], av[16];
#pragma unroll
        for (int r = 0; r < 16; r++) { aq[r]=0.f; ak[r]=0.f; av[r]=0.f; }
        for (int k = 0; k < CC; k++) {
            float wq = Wq[k*CC + c], wk = Wk[k*CC + c], wv = Wv[k*CC + c];
#pragma unroll
            for (int r = 0; r < 16; r++) {
                float am = Am[r*CC + k], ap = Ap[r*CC + k];
                aq[r] += am*wq; ak[r] += ap*wk; av[r] += am*wv;
            }
        }
        float bqv = bq[c], bkv = bk[c], bvv = bv[c];
#pragma unroll
        for (int r = 0; r < 16; r++) {
            g_q [(r0+r)*CC + c]       = aq[r] + bqv;
            g_kT[c*ROWS_TOT + r0 + r] = ak[r] + bkv;
            g_v [(r0+r)*CC + c]       = av[r] + bvv;
        }
    }
}

extern __shared__ char smem_raw[];

// ---------------- staging ----------------
__device__ __forceinline__ void ldgA(float4 pf[8], const float* __restrict__ Ag,
                                     int k0, int tid)
{
#pragma unroll
    for (int u = 0; u < 8; u++) {
        int idx = u*256 + tid;
        int row = idx >> 4, q4 = idx & 15;
        pf[u] = *(const float4*)(Ag + row*CC + k0 + q4*4);
    }
}

__device__ __forceinline__ void stsA(char* sm, const float4 pf[8], int tid)
{
#pragma unroll
    for (int u = 0; u < 8; u++) {
        int idx = u*256 + tid;
        int row = idx >> 4, q4 = idx & 15;
        uint32_t h01, l01, h23, l23;
        split2(pf[u].x, pf[u].y, h01, l01);
        split2(pf[u].z, pf[u].w, h23, l23);
        uint32_t boff = swz_off(row, q4*2);
        *(uint2*)(sm + OFF_AHI + boff) = make_uint2(h01, h23);
        *(uint2*)(sm + OFF_ALO + boff) = make_uint2(l01, l23);
    }
}

// Weight chunk via cp.async (2 x 32 KB), one commit group.
__device__ __forceinline__ void cpB(uint32_t sbase,
    const __nv_bfloat16* __restrict__ Whi, const __nv_bfloat16* __restrict__ Wlo,
    int k0, int tid)
{
#pragma unroll
    for (int u = 0; u < 8; u++) {
        int idx = u*256 + tid;
        int row = idx >> 3, q = idx & 7;
        uint32_t boff = swz_off(row, q*4);
        CP_ASYNC16(sbase + OFF_BHI + boff, Whi + row*CC + k0 + q*8);
        CP_ASYNC16(sbase + OFF_BLO + boff, Wlo + row*CC + k0 + q*8);
    }
    CP_COMMIT();
}

// MMA over staged K=64 chunk; warp tile 64x64 at (R0, C0), acc[4][8][4].
__device__ __forceinline__ void mma_chunk(const char* sm, float acc[4][8][4],
                                          int R0, int C0, int lane)
{
    const int lg = lane >> 2;
    const int lt = lane & 3;
#pragma unroll
    for (int kk = 0; kk < 4; kk++) {
        const int w0 = kk*8 + lt, w1 = w0 + 4;
        uint32_t ah[4][4], al[4][4];
#pragma unroll
        for (int mt = 0; mt < 4; mt++) {
            int r0 = R0 + mt*16 + lg, r1 = r0 + 8;
            uint32_t o00 = swz_off(r0, w0), o10 = swz_off(r1, w0);
            uint32_t o01 = swz_off(r0, w1), o11 = swz_off(r1, w1);
            ah[mt][0] = *(const uint32_t*)(sm + OFF_AHI + o00);
            ah[mt][1] = *(const uint32_t*)(sm + OFF_AHI + o10);
            ah[mt][2] = *(const uint32_t*)(sm + OFF_AHI + o01);
            ah[mt][3] = *(const uint32_t*)(sm + OFF_AHI + o11);
            al[mt][0] = *(const uint32_t*)(sm + OFF_ALO + o00);
            al[mt][1] = *(const uint32_t*)(sm + OFF_ALO + o10);
            al[mt][2] = *(const uint32_t*)(sm + OFF_ALO + o01);
            al[mt][3] = *(const uint32_t*)(sm + OFF_ALO + o11);
        }
#pragma unroll
        for (int nt = 0; nt < 8; nt++) {
            int n = C0 + nt*8 + lg;
            uint32_t ob0 = swz_off(n, w0), ob1 = swz_off(n, w1);
            uint32_t bh0 = *(const uint32_t*)(sm + OFF_BHI + ob0);
            uint32_t bh1 = *(const uint32_t*)(sm + OFF_BHI + ob1);
            uint32_t bl0 = *(const uint32_t*)(sm + OFF_BLO + ob0);
            uint32_t bl1 = *(const uint32_t*)(sm + OFF_BLO + ob1);
#pragma unroll
            for (int mt = 0; mt < 4; mt++) {
                mma_bf16(acc[mt][nt], ah[mt][0], ah[mt][1], ah[mt][2], ah[mt][3], bh0, bh1);
                mma_bf16(acc[mt][nt], ah[mt][0], ah[mt][1], ah[mt][2], ah[mt][3], bl0, bl1);
                mma_bf16(acc[mt][nt], al[mt][0], al[mt][1], al[mt][2], al[mt][3], bh0, bh1);
            }
        }
    }
}

#define ZERO_ACC(acc) \
    _Pragma("unroll") for (int mt = 0; mt < 4; mt++) \
    _Pragma("unroll") for (int nt = 0; nt < 8; nt++) \
    _Pragma("unroll") for (int i = 0; i < 4; i++) acc[mt][nt][i] = 0.f;

// ---------------- fused edge kernel, one CTA per (b,m) ----------------
__global__ __launch_bounds__(256, 1) void edge_kernel(
    const float* __restrict__ mol_adj, const float* __restrict__ prot_adj,
    const float* __restrict__ bka,  const float* __restrict__ bva,
    const float* __restrict__ boed, const float* __restrict__ bond,
    const float* __restrict__ Wond,
    float* __restrict__ out_node, float* __restrict__ out_edge,
    float* __restrict__ out_prot_adj)
{
    char* sm = smem_raw;
    const uint32_t sbase = smem_to_u32(sm);
    const int tid = threadIdx.x, wid = tid >> 5, lane = tid & 31;
    const int lg = lane >> 2, lt = lane & 3;
    const int bm = blockIdx.x, b = bm >> 7;
    const int warp_m = wid >> 2, warp_n = wid & 3;
    const int R0 = warp_m*64, C0 = warp_n*64;

    float* qs   = (float*)(sm + OFF_QS);
    float* attn = (float*)(sm + OFF_ATTN);

    const float* Ap = prot_adj + (size_t)bm*NN*CC;
    const float* Am = mol_adj  + (size_t)bm*NN*CC;

    qs[tid] = g_q[bm*CC + tid];

    // prot_adj passthrough (overlaps with compute)
    {
        const float4* src = (const float4*)Ap;
        float4* dst = (float4*)(out_prot_adj + (size_t)bm*NN*CC);
        for (int i = tid; i < NN*CC/4; i += 256) dst[i] = src[i];
    }

    float acc[4][8][4];
    float4 pf[8];

    // ---- prologue: prefetch prot chunk0 + Wka chunk0
    ldgA(pf, Ap, 0, tid);
    cpB(sbase, g_WkaT_hi, g_WkaT_lo, 0, tid);
    __syncthreads();     // qs + first-use ordering

    // ======== Phase A: prot_e ========
    ZERO_ACC(acc);
    for (int ch = 0; ch < 4; ch++) {
        stsA(sm, pf, tid);
        if (ch < 3) ldgA(pf, Ap, (ch+1)*64, tid);
        else        ldgA(pf, Am, 0, tid);          // cross-phase prefetch
        CP_WAIT0();
        __syncthreads();
        mma_chunk(sm, acc, R0, C0, lane);
        __syncthreads();
        if (ch < 3) cpB(sbase, g_WkaT_hi, g_WkaT_lo, (ch+1)*64, tid);
        else        cpB(sbase, g_WvaT_hi, g_WvaT_lo, 0, tid);
    }
    // epilogue A: attn := pe + bka + 1   (thread-local mapping)
#pragma unroll
    for (int mt = 0; mt < 4; mt++) {
        int r = R0 + mt*16 + lg;
#pragma unroll
        for (int nt = 0; nt < 8; nt++) {
            int c = C0 + nt*8 + lt*2;
            float b0v = __ldg(bka + c) + 1.0f, b1v = __ldg(bka + c + 1) + 1.0f;
            attn[r*ATTN_STR + c]       = acc[mt][nt][0] + b0v;
            attn[r*ATTN_STR + c + 1]   = acc[mt][nt][1] + b1v;
            attn[(r+8)*ATTN_STR + c]   = acc[mt][nt][2] + b0v;
            attn[(r+8)*ATTN_STR + c+1] = acc[mt][nt][3] + b1v;
        }
    }

    // ======== Phase B: mol_e ========
    ZERO_ACC(acc);
    for (int ch = 0; ch < 4; ch++) {
        stsA(sm, pf, tid);
        if (ch < 3) ldgA(pf, Am, (ch+1)*64, tid);
        CP_WAIT0();
        __syncthreads();
        mma_chunk(sm, acc, R0, C0, lane);
        __syncthreads();
        if (ch < 3) cpB(sbase, g_WvaT_hi, g_WvaT_lo, (ch+1)*64, tid);
        else        cpB(sbase, g_WoedT_hi, g_WoedT_lo, 0, tid);
    }
    // epilogue B: attn *= (me)*q*k/16   (thread-local read-modify-write)
    {
        const int bbase = b << 7;
#pragma unroll
        for (int mt = 0; mt < 4; mt++) {
            int r = R0 + mt*16 + lg;
#pragma unroll
            for (int nt = 0; nt < 8; nt++) {
                int c = C0 + nt*8 + lt*2;
                float bv0 = __ldg(bva + c), bv1 = __ldg(bva + c + 1);
                float q0 = qs[c] * 0.0625f, q1 = qs[c+1] * 0.0625f;
                float k00 = g_kT[c*ROWS_TOT + bbase + r];
                float k01 = g_kT[(c+1)*ROWS_TOT + bbase + r];
                float k10 = g_kT[c*ROWS_TOT + bbase + r + 8];
                float k11 = g_kT[(c+1)*ROWS_TOT + bbase + r + 8];
                attn[r*ATTN_STR + c]       *= (acc[mt][nt][0] + bv0) * q0 * k00;
                attn[r*ATTN_STR + c + 1]   *= (acc[mt][nt][1] + bv1) * q1 * k01;
                attn[(r+8)*ATTN_STR + c]   *= (acc[mt][nt][2] + bv0) * q0 * k10;
                attn[(r+8)*ATTN_STR + c+1] *= (acc[mt][nt][3] + bv1) * q1 * k11;
            }
        }
    }
    __syncthreads();     // attn complete before cross-thread reads

    // ======== Phase C: edge_out = attn @ Woed + boed ========
    ZERO_ACC(acc);
    {
        const int row = tid & 127, hk = tid >> 7;
        for (int ch = 0; ch < 4; ch++) {
            const int k0 = ch*64;
#pragma unroll
            for (int jj = 0; jj < 8; jj++) {
                int kloc = hk*32 + jj*4;
                const float* ap = attn + row*ATTN_STR + k0 + kloc;
                uint32_t h01, l01, h23, l23;
                split2(ap[0], ap[1], h01, l01);
                split2(ap[2], ap[3], h23, l23);
                uint32_t boff = swz_off(row, kloc >> 1);
                *(uint2*)(sm + OFF_AHI + boff) = make_uint2(h01, h23);
                *(uint2*)(sm + OFF_ALO + boff) = make_uint2(l01, l23);
            }
            CP_WAIT0();
            __syncthreads();
            mma_chunk(sm, acc, R0, C0, lane);
            __syncthreads();
            if (ch < 3) cpB(sbase, g_WoedT_hi, g_WoedT_lo, (ch+1)*64, tid);
        }
    }
    // epilogue C: direct float2 stores
#pragma unroll
    for (int mt = 0; mt < 4; mt++) {
        int r = R0 + mt*16 + lg;
#pragma unroll
        for (int nt = 0; nt < 8; nt++) {
            int c = C0 + nt*8 + lt*2;
            float b0v = __ldg(boed + c), b1v = __ldg(boed + c + 1);
            float2 o0 = make_float2(acc[mt][nt][0] + b0v, acc[mt][nt][1] + b1v);
            float2 o1 = make_float2(acc[mt][nt][2] + b0v, acc[mt][nt][3] + b1v);
            *(float2*)(out_edge + ((size_t)bm*NN + r)*CC + c)     = o0;
            *(float2*)(out_edge + ((size_t)bm*NN + r + 8)*CC + c) = o1;
        }
    }

    // ======== softmax over n (per channel) + node projection ========
    {
        const int c = tid;
        float mx = -1e30f;
        for (int n = 0; n < NN; n++) mx = fmaxf(mx, attn[n*ATTN_STR + c]);
        float s = 0.f, nv = 0.f;
        const float* vb = g_v + (size_t)(b << 7)*CC + c;
        for (int n = 0; n < NN; n++) {
            float e = __expf(attn[n*ATTN_STR + c] - mx);
            s += e;
            nv += e * vb[(size_t)n*CC];
        }
        float* nodes = (float*)(sm + OFF_AHI);
        nodes[c] = nv / s;
        __syncthreads();
        float acc2 = 0.f;
        for (int cc2 = 0; cc2 < CC; cc2++) acc2 += nodes[cc2] * Wond[cc2*CC + c];
        out_node[bm*CC + c] = acc2 + __ldg(bond + c);
    }
}

// ---------------- launch ----------------
extern "C" void kernel_launch(void* const* d_in, const int* in_sizes, int n_in,
                              void* d_out, int out_size)
{
    const float* mol_annot  = (const float*)d_in[0];
    const float* prot_annot = (const float*)d_in[1];
    const float* mol_adj    = (const float*)d_in[2];
    const float* prot_adj   = (const float*)d_in[3];
    const float* Wq   = (const float*)d_in[4];   const float* bq   = (const float*)d_in[5];
    const float* Wk   = (const float*)d_in[6];   const float* bk   = (const float*)d_in[7];
    const float* Wv   = (const float*)d_in[8];   const float* bv   = (const float*)d_in[9];
    const float* Wka  = (const float*)d_in[10];  const float* bka  = (const float*)d_in[11];
    const float* Wva  = (const float*)d_in[12];  const float* bva  = (const float*)d_in[13];
    const float* Wond = (const float*)d_in[14];  const float* bond = (const float*)d_in[15];
    const float* Woed = (const float*)d_in[16];  const float* boed = (const float*)d_in[17];

    float* out = (float*)d_out;
    const size_t ANNOT = (size_t)BB*NN*CC;          //   262144
    const size_t ADJ   = (size_t)BB*NN*NN*CC;       // 33554432
    float* out_node       = out;
    float* out_prot_annot = out + ANNOT;
    float* out_edge       = out + 2*ANNOT;
    float* out_prot_adj   = out + 2*ANNOT + ADJ;

    cudaFuncSetAttribute(edge_kernel,
                         cudaFuncAttributeMaxDynamicSharedMemorySize, SMEM_BYTES);

    cudaMemcpyAsync(out_prot_annot, prot_annot, ANNOT*sizeof(float),
                    cudaMemcpyDeviceToDevice, 0);

    prep_kernel<<<320, 256>>>(Wka, Wva, Woed,
                              mol_annot, prot_annot, Wq, bq, Wk, bk, Wv, bv);

    edge_kernel<<<ROWS_TOT, 256, SMEM_BYTES>>>(
        mol_adj, prot_adj, bka, bva, boed, bond, Wond,
        out_node, out_edge, out_prot_adj);
}

// round 5
// speedup vs baseline: 4.3658x; 1.0674x over previous
#include <cuda_runtime.h>
#include <cuda_bf16.h>
#include <stdint.h>
#include <math.h>

#define BB 8
#define NN 128
#define CC 256
#define ROWS_TOT (BB*NN)     /* 1024 */
#define CHK 32               /* K-chunk */
#define NCHK 8               /* chunks per phase */

// ---------------- scratch ----------------
__device__ float g_q[ROWS_TOT*CC];
__device__ float g_kT[CC*ROWS_TOT];
__device__ float g_v[ROWS_TOT*CC];
__device__ __align__(16) __nv_bfloat16 g_WkaT_hi[CC*CC];
__device__ __align__(16) __nv_bfloat16 g_WkaT_lo[CC*CC];
__device__ __align__(16) __nv_bfloat16 g_WvaT_hi[CC*CC];
__device__ __align__(16) __nv_bfloat16 g_WvaT_lo[CC*CC];
__device__ __align__(16) __nv_bfloat16 g_WoedT_hi[CC*CC];
__device__ __align__(16) __nv_bfloat16 g_WoedT_lo[CC*CC];

// ---------------- helpers ----------------
__device__ __forceinline__ void mma_bf16(float acc[4],
    uint32_t a0, uint32_t a1, uint32_t a2, uint32_t a3,
    uint32_t b0, uint32_t b1)
{
    asm volatile(
        "mma.sync.aligned.m16n8k16.row.col.f32.bf16.bf16.f32 "
        "{%0,%1,%2,%3}, {%4,%5,%6,%7}, {%8,%9}, {%0,%1,%2,%3};"
        : "+f"(acc[0]), "+f"(acc[1]), "+f"(acc[2]), "+f"(acc[3])
        : "r"(a0), "r"(a1), "r"(a2), "r"(a3), "r"(b0), "r"(b1));
}

__device__ __forceinline__ void split2(float a, float b, uint32_t& hi, uint32_t& lo) {
    __nv_bfloat16 ha = __float2bfloat16(a), hb = __float2bfloat16(b);
    __nv_bfloat162 h; h.x = ha; h.y = hb;
    hi = *reinterpret_cast<uint32_t*>(&h);
    __nv_bfloat162 l;
    l.x = __float2bfloat16(a - __bfloat162float(ha));
    l.y = __float2bfloat16(b - __bfloat162float(hb));
    lo = *reinterpret_cast<uint32_t*>(&l);
}

__device__ __forceinline__ uint32_t smem_to_u32(const void* p) {
    uint32_t a;
    asm("{ .reg .u64 t; cvta.to.shared.u64 t, %1; cvt.u32.u64 %0, t; }" : "=r"(a) : "l"(p));
    return a;
}

#define CP_ASYNC16(dst_u32, src_ptr) \
    asm volatile("cp.async.cg.shared.global [%0], [%1], 16;" \
        :: "r"(dst_u32), "l"(src_ptr) : "memory")
#define CP_COMMIT()  asm volatile("cp.async.commit_group;" ::: "memory")
#define CP_WAIT0()   asm volatile("cp.async.wait_group 0;" ::: "memory")

// Swizzle for 64-byte rows (32 bf16 = 16 words): word w of row r at
// byte r*64 + ((w ^ (((r>>1)&3)<<2))<<2). Conflict-free for 8-row x 4-word
// MMA fragment access and preserves 8/16-byte contiguity (xor touches bits>=2).
__device__ __forceinline__ uint32_t swz(int row, int w) {
    return (uint32_t)(row*64 + ((w ^ (((row >> 1) & 3) << 2)) << 2));
}

// ---------------- SMEM layout (bytes) ----------------
#define OFF_QS    0          /* 256 f32 */
#define OFF_NODES 1024       /* 256 f32 */
#define OFF_A     2048       /* 2 bufs x (hi 8K + lo 8K) = 32K */
#define ABUF_B    16384
#define OFF_B     34816      /* 2 bufs x (hi 16K + lo 16K) = 64K */
#define BBUF_B    32768
#define OFF_ATH   100352     /* attn hi: 8 chunks x 8K = 64K */
#define OFF_ATL   165888     /* attn lo: 64K */
#define SMEM_BYTES 231424

// ---------------- prep: weight transpose/split + qkv ----------------
__global__ __launch_bounds__(256) void prep_kernel(
    const float* __restrict__ Wka, const float* __restrict__ Wva,
    const float* __restrict__ Woed,
    const float* __restrict__ mol, const float* __restrict__ prot,
    const float* __restrict__ Wq, const float* __restrict__ bq,
    const float* __restrict__ Wk, const float* __restrict__ bk,
    const float* __restrict__ Wv, const float* __restrict__ bv)
{
    __shared__ float SH[8448];
    int tid = threadIdx.x;
    int bid = blockIdx.x;
    if (bid < 24) {
        // transpose + split one 32-row k-slab of one matrix
        int mat = bid >> 3, k0 = (bid & 7) * CHK;
        const float* W = (mat == 0) ? Wka : (mat == 1) ? Wva : Woed;
        __nv_bfloat16* GH = (mat == 0) ? g_WkaT_hi : (mat == 1) ? g_WvaT_hi : g_WoedT_hi;
        __nv_bfloat16* GL = (mat == 0) ? g_WkaT_lo : (mat == 1) ? g_WvaT_lo : g_WoedT_lo;
        for (int i = tid; i < 32*256; i += 256) {
            int kk = i >> 8, n = i & 255;
            SH[kk*257 + n] = W[(k0 + kk)*CC + n];
        }
        __syncthreads();
        int n = tid;
        uint32_t hi[16], lo[16];
#pragma unroll
        for (int j = 0; j < 16; j++)
            split2(SH[(2*j)*257 + n], SH[(2*j+1)*257 + n], hi[j], lo[j]);
        uint4* dh = (uint4*)(GH + n*CC + k0);
        uint4* dl = (uint4*)(GL + n*CC + k0);
#pragma unroll
        for (int j = 0; j < 4; j++) {
            dh[j] = make_uint4(hi[j*4], hi[j*4+1], hi[j*4+2], hi[j*4+3]);
            dl[j] = make_uint4(lo[j*4], lo[j*4+1], lo[j*4+2], lo[j*4+3]);
        }
    } else {
        float* Am = SH;
        float* Ap = SH + 4224;
        int r0 = (bid - 24) * 16;
        for (int i = tid; i < 16*CC; i += 256) {
            int r = i >> 8, c = i & 255;
            Am[i] = mol [(r0 + r)*CC + c];
            Ap[i] = prot[(r0 + r)*CC + c];
        }
        __syncthreads();
        int c = tid;
        float aq[16], ak[16], av[16];
#pragma unroll
        for (int r = 0; r < 16; r++) { aq[r]=0.f; ak[r]=0.f; av[r]=0.f; }
        for (int k = 0; k < CC; k++) {
            float wq = Wq[k*CC + c], wk = Wk[k*CC + c], wv = Wv[k*CC + c];
#pragma unroll
            for (int r = 0; r < 16; r++) {
                float am = Am[r*CC + k], ap = Ap[r*CC + k];
                aq[r] += am*wq; ak[r] += ap*wk; av[r] += am*wv;
            }
        }
        float bqv = bq[c], bkv = bk[c], bvv = bv[c];
#pragma unroll
        for (int r = 0; r < 16; r++) {
            g_q [(r0+r)*CC + c]       = aq[r] + bqv;
            g_kT[c*ROWS_TOT + r0 + r] = ak[r] + bkv;
            g_v [(r0+r)*CC + c]       = av[r] + bvv;
        }
    }
}

extern __shared__ char smem_raw[];

// ---------------- staging ----------------
__device__ __forceinline__ void ldgA(float4 pf[4], const float* __restrict__ Ag,
                                     int k0, int tid)
{
#pragma unroll
    for (int u = 0; u < 4; u++) {
        int idx = u*256 + tid;
        int row = idx >> 3, j = idx & 7;
        pf[u] = *(const float4*)(Ag + row*CC + k0 + j*4);
    }
}

// split+store A chunk; optionally also write raw fp32 to out (prot passthrough)
__device__ __forceinline__ void stsA(char* ab, const float4 pf[4], int tid,
                                     float* __restrict__ outp, int k0)
{
#pragma unroll
    for (int u = 0; u < 4; u++) {
        int idx = u*256 + tid;
        int row = idx >> 3, j = idx & 7;
        uint32_t h01, l01, h23, l23;
        split2(pf[u].x, pf[u].y, h01, l01);
        split2(pf[u].z, pf[u].w, h23, l23);
        uint32_t boff = swz(row, j*2);
        *(uint2*)(ab + boff)        = make_uint2(h01, h23);
        *(uint2*)(ab + 8192 + boff) = make_uint2(l01, l23);
        if (outp) *(float4*)(outp + row*CC + k0 + j*4) = pf[u];
    }
}

__device__ __forceinline__ void cpB(uint32_t bb,
    const __nv_bfloat16* __restrict__ Whi, const __nv_bfloat16* __restrict__ Wlo,
    int k0, int tid)
{
#pragma unroll
    for (int u = 0; u < 4; u++) {
        int idx = u*256 + tid;
        int row = idx >> 2, t = idx & 3;
        uint32_t boff = swz(row, t*4);
        CP_ASYNC16(bb + boff,         Whi + row*CC + k0 + t*8);
        CP_ASYNC16(bb + 16384 + boff, Wlo + row*CC + k0 + t*8);
    }
    CP_COMMIT();
}

// MMA over a staged K=32 chunk. A from (ah_b, al_b), B from (bh_b, bl_b).
// hi-pass then lo-pass to halve live fragment registers.
__device__ __forceinline__ void mma_chunk(
    const char* ah_b, const char* al_b, const char* bh_b, const char* bl_b,
    float acc[4][8][4], int R0, int C0, int lane)
{
    const int lg = lane >> 2, lt = lane & 3;
#pragma unroll
    for (int kk = 0; kk < 2; kk++) {
        const int w0 = kk*8 + lt, w1 = w0 + 4;
        uint32_t af[4][4];
#pragma unroll
        for (int mt = 0; mt < 4; mt++) {
            int r0 = R0 + mt*16 + lg, r1 = r0 + 8;
            af[mt][0] = *(const uint32_t*)(ah_b + swz(r0, w0));
            af[mt][1] = *(const uint32_t*)(ah_b + swz(r1, w0));
            af[mt][2] = *(const uint32_t*)(ah_b + swz(r0, w1));
            af[mt][3] = *(const uint32_t*)(ah_b + swz(r1, w1));
        }
#pragma unroll
        for (int nt = 0; nt < 8; nt++) {
            int n = C0 + nt*8 + lg;
            uint32_t ob0 = swz(n, w0), ob1 = swz(n, w1);
            uint32_t bh0 = *(const uint32_t*)(bh_b + ob0);
            uint32_t bh1 = *(const uint32_t*)(bh_b + ob1);
            uint32_t bl0 = *(const uint32_t*)(bl_b + ob0);
            uint32_t bl1 = *(const uint32_t*)(bl_b + ob1);
#pragma unroll
            for (int mt = 0; mt < 4; mt++) {
                mma_bf16(acc[mt][nt], af[mt][0], af[mt][1], af[mt][2], af[mt][3], bh0, bh1);
                mma_bf16(acc[mt][nt], af[mt][0], af[mt][1], af[mt][2], af[mt][3], bl0, bl1);
            }
        }
        // lo-pass: reload fragments from A-lo, multiply by B-hi only
#pragma unroll
        for (int mt = 0; mt < 4; mt++) {
            int r0 = R0 + mt*16 + lg, r1 = r0 + 8;
            af[mt][0] = *(const uint32_t*)(al_b + swz(r0, w0));
            af[mt][1] = *(const uint32_t*)(al_b + swz(r1, w0));
            af[mt][2] = *(const uint32_t*)(al_b + swz(r0, w1));
            af[mt][3] = *(const uint32_t*)(al_b + swz(r1, w1));
        }
#pragma unroll
        for (int nt = 0; nt < 8; nt++) {
            int n = C0 + nt*8 + lg;
            uint32_t bh0 = *(const uint32_t*)(bh_b + swz(n, w0));
            uint32_t bh1 = *(const uint32_t*)(bh_b + swz(n, w1));
#pragma unroll
            for (int mt = 0; mt < 4; mt++)
                mma_bf16(acc[mt][nt], af[mt][0], af[mt][1], af[mt][2], af[mt][3], bh0, bh1);
        }
    }
}

#define ZERO_ACC(acc) \
    _Pragma("unroll") for (int mt = 0; mt < 4; mt++) \
    _Pragma("unroll") for (int nt = 0; nt < 8; nt++) \
    _Pragma("unroll") for (int i = 0; i < 4; i++) acc[mt][nt][i] = 0.f;

__device__ __forceinline__ float rec_half(uint32_t uh, uint32_t ul, int odd) {
    return odd ? (__uint_as_float(uh & 0xffff0000u) + __uint_as_float(ul & 0xffff0000u))
               : (__uint_as_float(uh << 16) + __uint_as_float(ul << 16));
}

// ---------------- fused edge kernel, one CTA per (b,m) ----------------
__global__ __launch_bounds__(256, 1) void edge_kernel(
    const float* __restrict__ mol_adj, const float* __restrict__ prot_adj,
    const float* __restrict__ bka,  const float* __restrict__ bva,
    const float* __restrict__ boed, const float* __restrict__ bond,
    const float* __restrict__ Wond,
    float* __restrict__ out_node, float* __restrict__ out_edge,
    float* __restrict__ out_prot_adj)
{
    char* sm = smem_raw;
    const uint32_t sbase = smem_to_u32(sm);
    const int tid = threadIdx.x, wid = tid >> 5, lane = tid & 31;
    const int lg = lane >> 2, lt = lane & 3;
    const int bm = blockIdx.x, b = bm >> 7;
    const int R0 = (wid >> 2)*64, C0 = (wid & 3)*64;

    float* qs = (float*)(sm + OFF_QS);
    const float* Ap = prot_adj + (size_t)bm*NN*CC;
    const float* Am = mol_adj  + (size_t)bm*NN*CC;
    float* outp = out_prot_adj + (size_t)bm*NN*CC;

    qs[tid] = g_q[bm*CC + tid];

    float acc[4][8][4];
    float4 pf[4];

    // prologue
    ldgA(pf, Ap, 0, tid);
    cpB(sbase + OFF_B, g_WkaT_hi, g_WkaT_lo, 0, tid);
    __syncthreads();

    // ======== Phase A: prot_e (writes prot passthrough from pf) ========
    ZERO_ACC(acc);
    for (int ch = 0; ch < NCHK; ch++) {
        char* ab = sm + OFF_A + (ch & 1)*ABUF_B;
        stsA(ab, pf, tid, outp, ch*CHK);
        if (ch < 7) ldgA(pf, Ap, (ch+1)*CHK, tid);
        else        ldgA(pf, Am, 0, tid);
        CP_WAIT0();
        __syncthreads();
        uint32_t nb = sbase + OFF_B + (((ch & 1) ^ 1))*BBUF_B;
        if (ch < 7) cpB(nb, g_WkaT_hi, g_WkaT_lo, (ch+1)*CHK, tid);
        else        cpB(nb, g_WvaT_hi, g_WvaT_lo, 0, tid);
        const char* bb = sm + OFF_B + (ch & 1)*BBUF_B;
        mma_chunk(ab, ab + 8192, bb, bb + 16384, acc, R0, C0, lane);
    }
    // epilogue A: write split(pe + bka + 1) to attn hi/lo
#pragma unroll
    for (int mt = 0; mt < 4; mt++) {
        int r = R0 + mt*16 + lg;
#pragma unroll
        for (int nt = 0; nt < 8; nt++) {
            int c = C0 + nt*8 + lt*2;
            uint32_t coff = ((uint32_t)(c >> 5))*8192u;
            int wloc = (c & 31) >> 1;
            float b0v = __ldg(bka + c) + 1.0f, b1v = __ldg(bka + c + 1) + 1.0f;
            uint32_t h, l;
            uint32_t o0 = coff + swz(r, wloc), o1 = coff + swz(r + 8, wloc);
            split2(acc[mt][nt][0] + b0v, acc[mt][nt][1] + b1v, h, l);
            *(uint32_t*)(sm + OFF_ATH + o0) = h;
            *(uint32_t*)(sm + OFF_ATL + o0) = l;
            split2(acc[mt][nt][2] + b0v, acc[mt][nt][3] + b1v, h, l);
            *(uint32_t*)(sm + OFF_ATH + o1) = h;
            *(uint32_t*)(sm + OFF_ATL + o1) = l;
        }
    }

    // ======== Phase B: mol_e ========
    ZERO_ACC(acc);
    for (int ch = 0; ch < NCHK; ch++) {
        char* ab = sm + OFF_A + (ch & 1)*ABUF_B;
        stsA(ab, pf, tid, (float*)0, 0);
        if (ch < 7) ldgA(pf, Am, (ch+1)*CHK, tid);
        CP_WAIT0();
        __syncthreads();
        uint32_t nb = sbase + OFF_B + (((ch & 1) ^ 1))*BBUF_B;
        if (ch < 7) cpB(nb, g_WvaT_hi, g_WvaT_lo, (ch+1)*CHK, tid);
        else        cpB(nb, g_WoedT_hi, g_WoedT_lo, 0, tid);
        const char* bb = sm + OFF_B + (ch & 1)*BBUF_B;
        mma_chunk(ab, ab + 8192, bb, bb + 16384, acc, R0, C0, lane);
    }
    // epilogue B: attn = pe * (me + bva) * q * k / 16, re-split in place
    {
        const int bbase = b << 7;
#pragma unroll
        for (int mt = 0; mt < 4; mt++) {
            int r = R0 + mt*16 + lg;
#pragma unroll
            for (int nt = 0; nt < 8; nt++) {
                int c = C0 + nt*8 + lt*2;
                uint32_t coff = ((uint32_t)(c >> 5))*8192u;
                int wloc = (c & 31) >> 1;
                uint32_t o0 = coff + swz(r, wloc), o1 = coff + swz(r + 8, wloc);
                float bv0 = __ldg(bva + c), bv1 = __ldg(bva + c + 1);
                float q0 = qs[c] * 0.0625f, q1 = qs[c+1] * 0.0625f;
                float k00 = g_kT[c*ROWS_TOT + bbase + r];
                float k01 = g_kT[(c+1)*ROWS_TOT + bbase + r];
                float k10 = g_kT[c*ROWS_TOT + bbase + r + 8];
                float k11 = g_kT[(c+1)*ROWS_TOT + bbase + r + 8];
                uint32_t uh0 = *(uint32_t*)(sm + OFF_ATH + o0);
                uint32_t ul0 = *(uint32_t*)(sm + OFF_ATL + o0);
                uint32_t uh1 = *(uint32_t*)(sm + OFF_ATH + o1);
                uint32_t ul1 = *(uint32_t*)(sm + OFF_ATL + o1);
                float p00 = rec_half(uh0, ul0, 0), p01 = rec_half(uh0, ul0, 1);
                float p10 = rec_half(uh1, ul1, 0), p11 = rec_half(uh1, ul1, 1);
                float a0 = p00 * (acc[mt][nt][0] + bv0) * q0 * k00;
                float a1 = p01 * (acc[mt][nt][1] + bv1) * q1 * k01;
                float a2 = p10 * (acc[mt][nt][2] + bv0) * q0 * k10;
                float a3 = p11 * (acc[mt][nt][3] + bv1) * q1 * k11;
                uint32_t h, l;
                split2(a0, a1, h, l);
                *(uint32_t*)(sm + OFF_ATH + o0) = h;
                *(uint32_t*)(sm + OFF_ATL + o0) = l;
                split2(a2, a3, h, l);
                *(uint32_t*)(sm + OFF_ATH + o1) = h;
                *(uint32_t*)(sm + OFF_ATL + o1) = l;
            }
        }
    }

    // ======== Phase C: edge_out = attn @ Woed + boed (no A staging!) ========
    ZERO_ACC(acc);
    for (int ch = 0; ch < NCHK; ch++) {
        CP_WAIT0();
        __syncthreads();
        uint32_t nb = sbase + OFF_B + (((ch & 1) ^ 1))*BBUF_B;
        if (ch < 7) cpB(nb, g_WoedT_hi, g_WoedT_lo, (ch+1)*CHK, tid);
        const char* ah = sm + OFF_ATH + ch*8192;
        const char* al = sm + OFF_ATL + ch*8192;
        const char* bb = sm + OFF_B + (ch & 1)*BBUF_B;
        mma_chunk(ah, al, bb, bb + 16384, acc, R0, C0, lane);
    }
    // epilogue C: direct stores
#pragma unroll
    for (int mt = 0; mt < 4; mt++) {
        int r = R0 + mt*16 + lg;
#pragma unroll
        for (int nt = 0; nt < 8; nt++) {
            int c = C0 + nt*8 + lt*2;
            float b0v = __ldg(boed + c), b1v = __ldg(boed + c + 1);
            *(float2*)(out_edge + ((size_t)bm*NN + r)*CC + c) =
                make_float2(acc[mt][nt][0] + b0v, acc[mt][nt][1] + b1v);
            *(float2*)(out_edge + ((size_t)bm*NN + r + 8)*CC + c) =
                make_float2(acc[mt][nt][2] + b0v, acc[mt][nt][3] + b1v);
        }
    }

    // ======== softmax over n (per channel) + node projection ========
    {
        const int c = tid;
        const int odd = c & 1;
        const int wloc = (c & 31) >> 1;
        const char* bh = sm + OFF_ATH + ((uint32_t)(c >> 5))*8192u;
        const char* bl = sm + OFF_ATL + ((uint32_t)(c >> 5))*8192u;
        float mx = -1e30f;
#pragma unroll 4
        for (int n = 0; n < NN; n++) {
            uint32_t off = swz(n, wloc);
            float v = rec_half(*(const uint32_t*)(bh + off),
                               *(const uint32_t*)(bl + off), odd);
            mx = fmaxf(mx, v);
        }
        float s = 0.f, nv = 0.f;
        const float* vb = g_v + (size_t)(b << 7)*CC + c;
#pragma unroll 4
        for (int n = 0; n < NN; n++) {
            uint32_t off = swz(n, wloc);
            float v = rec_half(*(const uint32_t*)(bh + off),
                               *(const uint32_t*)(bl + off), odd);
            float e = __expf(v - mx);
            s += e;
            nv += e * vb[(size_t)n*CC];
        }
        float* nodes = (float*)(sm + OFF_NODES);
        nodes[c] = nv / s;
        __syncthreads();
        float acc2 = 0.f;
#pragma unroll 4
        for (int cc2 = 0; cc2 < CC; cc2++) acc2 += nodes[cc2] * Wond[cc2*CC + c];
        out_node[bm*CC + c] = acc2 + __ldg(bond + c);
    }
}

// ---------------- launch ----------------
extern "C" void kernel_launch(void* const* d_in, const int* in_sizes, int n_in,
                              void* d_out, int out_size)
{
    const float* mol_annot  = (const float*)d_in[0];
    const float* prot_annot = (const float*)d_in[1];
    const float* mol_adj    = (const float*)d_in[2];
    const float* prot_adj   = (const float*)d_in[3];
    const float* Wq   = (const float*)d_in[4];   const float* bq   = (const float*)d_in[5];
    const float* Wk   = (const float*)d_in[6];   const float* bk   = (const float*)d_in[7];
    const float* Wv   = (const float*)d_in[8];   const float* bv   = (const float*)d_in[9];
    const float* Wka  = (const float*)d_in[10];  const float* bka  = (const float*)d_in[11];
    const float* Wva  = (const float*)d_in[12];  const float* bva  = (const float*)d_in[13];
    const float* Wond = (const float*)d_in[14];  const float* bond = (const float*)d_in[15];
    const float* Woed = (const float*)d_in[16];  const float* boed = (const float*)d_in[17];

    float* out = (float*)d_out;
    const size_t ANNOT = (size_t)BB*NN*CC;
    const size_t ADJ   = (size_t)BB*NN*NN*CC;
    float* out_node       = out;
    float* out_prot_annot = out + ANNOT;
    float* out_edge       = out + 2*ANNOT;
    float* out_prot_adj   = out + 2*ANNOT + ADJ;

    cudaFuncSetAttribute(edge_kernel,
                         cudaFuncAttributeMaxDynamicSharedMemorySize, SMEM_BYTES);

    cudaMemcpyAsync(out_prot_annot, prot_annot, ANNOT*sizeof(float),
                    cudaMemcpyDeviceToDevice, 0);

    prep_kernel<<<88, 256>>>(Wka, Wva, Woed,
                             mol_annot, prot_annot, Wq, bq, Wk, bk, Wv, bv);

    edge_kernel<<<ROWS_TOT, 256, SMEM_BYTES>>>(
        mol_adj, prot_adj, bka, bva, boed, bond, Wond,
        out_node, out_edge, out_prot_adj);
}

// round 6
// speedup vs baseline: 4.7299x; 1.0834x over previous
#include <cuda_runtime.h>
#include <cuda_bf16.h>
#include <stdint.h>
#include <math.h>

#define BB 8
#define NN 128
#define CC 256
#define ROWS_TOT (BB*NN)     /* 1024 */
#define CHK 32               /* K-chunk */
#define NCHK 8               /* chunks per phase */
#define THREADS 512

// ---------------- scratch ----------------
__device__ float g_q[ROWS_TOT*CC];
__device__ float g_kT[CC*ROWS_TOT];
__device__ float g_v[ROWS_TOT*CC];
__device__ __align__(16) __nv_bfloat16 g_WkaT_hi[CC*CC];
__device__ __align__(16) __nv_bfloat16 g_WkaT_lo[CC*CC];
__device__ __align__(16) __nv_bfloat16 g_WvaT_hi[CC*CC];
__device__ __align__(16) __nv_bfloat16 g_WvaT_lo[CC*CC];
__device__ __align__(16) __nv_bfloat16 g_WoedT_hi[CC*CC];
__device__ __align__(16) __nv_bfloat16 g_WoedT_lo[CC*CC];

// ---------------- helpers ----------------
__device__ __forceinline__ void mma_bf16(float acc[4],
    uint32_t a0, uint32_t a1, uint32_t a2, uint32_t a3,
    uint32_t b0, uint32_t b1)
{
    asm volatile(
        "mma.sync.aligned.m16n8k16.row.col.f32.bf16.bf16.f32 "
        "{%0,%1,%2,%3}, {%4,%5,%6,%7}, {%8,%9}, {%0,%1,%2,%3};"
        : "+f"(acc[0]), "+f"(acc[1]), "+f"(acc[2]), "+f"(acc[3])
        : "r"(a0), "r"(a1), "r"(a2), "r"(a3), "r"(b0), "r"(b1));
}

__device__ __forceinline__ void split2(float a, float b, uint32_t& hi, uint32_t& lo) {
    __nv_bfloat16 ha = __float2bfloat16(a), hb = __float2bfloat16(b);
    __nv_bfloat162 h; h.x = ha; h.y = hb;
    hi = *reinterpret_cast<uint32_t*>(&h);
    __nv_bfloat162 l;
    l.x = __float2bfloat16(a - __bfloat162float(ha));
    l.y = __float2bfloat16(b - __bfloat162float(hb));
    lo = *reinterpret_cast<uint32_t*>(&l);
}

__device__ __forceinline__ uint32_t smem_to_u32(const void* p) {
    uint32_t a;
    asm("{ .reg .u64 t; cvta.to.shared.u64 t, %1; cvt.u32.u64 %0, t; }" : "=r"(a) : "l"(p));
    return a;
}

#define CP_ASYNC16(dst_u32, src_ptr) \
    asm volatile("cp.async.cg.shared.global [%0], [%1], 16;" \
        :: "r"(dst_u32), "l"(src_ptr) : "memory")
#define CP_COMMIT()  asm volatile("cp.async.commit_group;" ::: "memory")
#define CP_WAIT0()   asm volatile("cp.async.wait_group 0;" ::: "memory")

// Swizzle for 64-byte rows (32 bf16 = 16 words)
__device__ __forceinline__ uint32_t swz(int row, int w) {
    return (uint32_t)(row*64 + ((w ^ (((row >> 1) & 3) << 2)) << 2));
}

// ---------------- SMEM layout (bytes) ----------------
#define OFF_QS    0
#define OFF_NODES 1024
#define OFF_A     2048       /* 2 bufs x (hi 8K + lo 8K) = 32K; reused as reduce scratch */
#define ABUF_B    16384
#define OFF_B     34816      /* 2 bufs x (hi 16K + lo 16K) = 64K */
#define BBUF_B    32768
#define OFF_ATH   100352     /* attn hi: 8 chunks x 8K */
#define OFF_ATL   165888     /* attn lo */
#define SMEM_BYTES 231424

// ---------------- prep: weight transpose/split + qkv + prot_annot copy ------
__global__ __launch_bounds__(256) void prep_kernel(
    const float* __restrict__ Wka, const float* __restrict__ Wva,
    const float* __restrict__ Woed,
    const float* __restrict__ mol, const float* __restrict__ prot,
    const float* __restrict__ Wq, const float* __restrict__ bq,
    const float* __restrict__ Wk, const float* __restrict__ bk,
    const float* __restrict__ Wv, const float* __restrict__ bv,
    float* __restrict__ out_prot_annot)
{
    __shared__ float SH[8448];
    int tid = threadIdx.x;
    int bid = blockIdx.x;
    if (bid < 24) {
        int mat = bid >> 3, k0 = (bid & 7) * CHK;
        const float* W = (mat == 0) ? Wka : (mat == 1) ? Wva : Woed;
        __nv_bfloat16* GH = (mat == 0) ? g_WkaT_hi : (mat == 1) ? g_WvaT_hi : g_WoedT_hi;
        __nv_bfloat16* GL = (mat == 0) ? g_WkaT_lo : (mat == 1) ? g_WvaT_lo : g_WoedT_lo;
        for (int i = tid; i < 32*256; i += 256) {
            int kk = i >> 8, n = i & 255;
            SH[kk*257 + n] = W[(k0 + kk)*CC + n];
        }
        __syncthreads();
        int n = tid;
        uint32_t hi[16], lo[16];
#pragma unroll
        for (int j = 0; j < 16; j++)
            split2(SH[(2*j)*257 + n], SH[(2*j+1)*257 + n], hi[j], lo[j]);
        uint4* dh = (uint4*)(GH + n*CC + k0);
        uint4* dl = (uint4*)(GL + n*CC + k0);
#pragma unroll
        for (int j = 0; j < 4; j++) {
            dh[j] = make_uint4(hi[j*4], hi[j*4+1], hi[j*4+2], hi[j*4+3]);
            dl[j] = make_uint4(lo[j*4], lo[j*4+1], lo[j*4+2], lo[j*4+3]);
        }
    } else if (bid < 88) {
        float* Am = SH;
        float* Ap = SH + 4224;
        int r0 = (bid - 24) * 16;
        for (int i = tid; i < 16*CC; i += 256) {
            int r = i >> 8, c = i & 255;
            Am[i] = mol [(r0 + r)*CC + c];
            Ap[i] = prot[(r0 + r)*CC + c];
        }
        __syncthreads();
        int c = tid;
        float aq[16], ak[16], av[16];
#pragma unroll
        for (int r = 0; r < 16; r++) { aq[r]=0.f; ak[r]=0.f; av[r]=0.f; }
        for (int k = 0; k < CC; k++) {
            float wq = Wq[k*CC + c], wk = Wk[k*CC + c], wv = Wv[k*CC + c];
#pragma unroll
            for (int r = 0; r < 16; r++) {
                float am = Am[r*CC + k], ap = Ap[r*CC + k];
                aq[r] += am*wq; ak[r] += ap*wk; av[r] += am*wv;
            }
        }
        float bqv = bq[c], bkv = bk[c], bvv = bv[c];
#pragma unroll
        for (int r = 0; r < 16; r++) {
            g_q [(r0+r)*CC + c]       = aq[r] + bqv;
            g_kT[c*ROWS_TOT + r0 + r] = ak[r] + bkv;
            g_v [(r0+r)*CC + c]       = av[r] + bvv;
        }
    } else {
        // prot_annot passthrough: 65536 float4 over 32 blocks
        const float4* src = (const float4*)prot;
        float4* dst = (float4*)out_prot_annot;
        int base = (bid - 88) * 2048;
#pragma unroll
        for (int u = 0; u < 8; u++)
            dst[base + u*256 + tid] = src[base + u*256 + tid];
    }
}

extern __shared__ char smem_raw[];

// ---------------- staging (512 threads) ----------------
__device__ __forceinline__ void ldgA(float4 pf[2], const float* __restrict__ Ag,
                                     int k0, int tid)
{
#pragma unroll
    for (int u = 0; u < 2; u++) {
        int idx = u*THREADS + tid;
        int row = idx >> 3, j = idx & 7;
        pf[u] = *(const float4*)(Ag + row*CC + k0 + j*4);
    }
}

__device__ __forceinline__ void stsA(char* ab, const float4 pf[2], int tid,
                                     float* __restrict__ outp, int k0)
{
#pragma unroll
    for (int u = 0; u < 2; u++) {
        int idx = u*THREADS + tid;
        int row = idx >> 3, j = idx & 7;
        uint32_t h01, l01, h23, l23;
        split2(pf[u].x, pf[u].y, h01, l01);
        split2(pf[u].z, pf[u].w, h23, l23);
        uint32_t boff = swz(row, j*2);
        *(uint2*)(ab + boff)        = make_uint2(h01, h23);
        *(uint2*)(ab + 8192 + boff) = make_uint2(l01, l23);
        if (outp) *(float4*)(outp + row*CC + k0 + j*4) = pf[u];
    }
}

__device__ __forceinline__ void cpB(uint32_t bb,
    const __nv_bfloat16* __restrict__ Whi, const __nv_bfloat16* __restrict__ Wlo,
    int k0, int tid)
{
#pragma unroll
    for (int u = 0; u < 2; u++) {
        int idx = u*THREADS + tid;
        int row = idx >> 2, t = idx & 3;
        uint32_t boff = swz(row, t*4);
        CP_ASYNC16(bb + boff,         Whi + row*CC + k0 + t*8);
        CP_ASYNC16(bb + 16384 + boff, Wlo + row*CC + k0 + t*8);
    }
    CP_COMMIT();
}

// MMA over staged K=32 chunk; warp tile 32x64, acc[2][8][4].
__device__ __forceinline__ void mma_chunk(
    const char* ah_b, const char* al_b, const char* bh_b, const char* bl_b,
    float acc[2][8][4], int R0, int C0, int lane)
{
    const int lg = lane >> 2, lt = lane & 3;
#pragma unroll
    for (int kk = 0; kk < 2; kk++) {
        const int w0 = kk*8 + lt, w1 = w0 + 4;
        uint32_t af[2][4];
#pragma unroll
        for (int mt = 0; mt < 2; mt++) {
            int r0 = R0 + mt*16 + lg, r1 = r0 + 8;
            af[mt][0] = *(const uint32_t*)(ah_b + swz(r0, w0));
            af[mt][1] = *(const uint32_t*)(ah_b + swz(r1, w0));
            af[mt][2] = *(const uint32_t*)(ah_b + swz(r0, w1));
            af[mt][3] = *(const uint32_t*)(ah_b + swz(r1, w1));
        }
#pragma unroll
        for (int nt = 0; nt < 8; nt++) {
            int n = C0 + nt*8 + lg;
            uint32_t ob0 = swz(n, w0), ob1 = swz(n, w1);
            uint32_t bh0 = *(const uint32_t*)(bh_b + ob0);
            uint32_t bh1 = *(const uint32_t*)(bh_b + ob1);
            uint32_t bl0 = *(const uint32_t*)(bl_b + ob0);
            uint32_t bl1 = *(const uint32_t*)(bl_b + ob1);
#pragma unroll
            for (int mt = 0; mt < 2; mt++) {
                mma_bf16(acc[mt][nt], af[mt][0], af[mt][1], af[mt][2], af[mt][3], bh0, bh1);
                mma_bf16(acc[mt][nt], af[mt][0], af[mt][1], af[mt][2], af[mt][3], bl0, bl1);
            }
        }
        // lo-pass
#pragma unroll
        for (int mt = 0; mt < 2; mt++) {
            int r0 = R0 + mt*16 + lg, r1 = r0 + 8;
            af[mt][0] = *(const uint32_t*)(al_b + swz(r0, w0));
            af[mt][1] = *(const uint32_t*)(al_b + swz(r1, w0));
            af[mt][2] = *(const uint32_t*)(al_b + swz(r0, w1));
            af[mt][3] = *(const uint32_t*)(al_b + swz(r1, w1));
        }
#pragma unroll
        for (int nt = 0; nt < 8; nt++) {
            int n = C0 + nt*8 + lg;
            uint32_t bh0 = *(const uint32_t*)(bh_b + swz(n, w0));
            uint32_t bh1 = *(const uint32_t*)(bh_b + swz(n, w1));
#pragma unroll
            for (int mt = 0; mt < 2; mt++)
                mma_bf16(acc[mt][nt], af[mt][0], af[mt][1], af[mt][2], af[mt][3], bh0, bh1);
        }
    }
}

#define ZERO_ACC(acc) \
    _Pragma("unroll") for (int mt = 0; mt < 2; mt++) \
    _Pragma("unroll") for (int nt = 0; nt < 8; nt++) \
    _Pragma("unroll") for (int i = 0; i < 4; i++) acc[mt][nt][i] = 0.f;

__device__ __forceinline__ float rec_half(uint32_t uh, uint32_t ul, int odd) {
    return odd ? (__uint_as_float(uh & 0xffff0000u) + __uint_as_float(ul & 0xffff0000u))
               : (__uint_as_float(uh << 16) + __uint_as_float(ul << 16));
}

// ---------------- fused edge kernel, one CTA per (b,m), 512 threads ---------
__global__ __launch_bounds__(THREADS, 1) void edge_kernel(
    const float* __restrict__ mol_adj, const float* __restrict__ prot_adj,
    const float* __restrict__ bka,  const float* __restrict__ bva,
    const float* __restrict__ boed, const float* __restrict__ bond,
    const float* __restrict__ Wond,
    float* __restrict__ out_node, float* __restrict__ out_edge,
    float* __restrict__ out_prot_adj)
{
    char* sm = smem_raw;
    const uint32_t sbase = smem_to_u32(sm);
    const int tid = threadIdx.x, wid = tid >> 5, lane = tid & 31;
    const int lg = lane >> 2, lt = lane & 3;
    const int bm = blockIdx.x, b = bm >> 7;
    const int R0 = (wid >> 2)*32, C0 = (wid & 3)*64;   // 4x4 warp grid

    float* qs = (float*)(sm + OFF_QS);
    const float* Ap = prot_adj + (size_t)bm*NN*CC;
    const float* Am = mol_adj  + (size_t)bm*NN*CC;
    float* outp = out_prot_adj + (size_t)bm*NN*CC;

    if (tid < 256) qs[tid] = g_q[bm*CC + tid];

    float acc[2][8][4];
    float4 pf[2];

    // prologue
    ldgA(pf, Ap, 0, tid);
    cpB(sbase + OFF_B, g_WkaT_hi, g_WkaT_lo, 0, tid);
    __syncthreads();

    // ======== Phase A: prot_e (writes prot passthrough from pf) ========
    ZERO_ACC(acc);
    for (int ch = 0; ch < NCHK; ch++) {
        char* ab = sm + OFF_A + (ch & 1)*ABUF_B;
        stsA(ab, pf, tid, outp, ch*CHK);
        if (ch < 7) ldgA(pf, Ap, (ch+1)*CHK, tid);
        else        ldgA(pf, Am, 0, tid);
        CP_WAIT0();
        __syncthreads();
        uint32_t nb = sbase + OFF_B + (((ch & 1) ^ 1))*BBUF_B;
        if (ch < 7) cpB(nb, g_WkaT_hi, g_WkaT_lo, (ch+1)*CHK, tid);
        else        cpB(nb, g_WvaT_hi, g_WvaT_lo, 0, tid);
        const char* bb = sm + OFF_B + (ch & 1)*BBUF_B;
        mma_chunk(ab, ab + 8192, bb, bb + 16384, acc, R0, C0, lane);
    }
    // epilogue A: split(pe + bka + 1) into attn hi/lo
#pragma unroll
    for (int mt = 0; mt < 2; mt++) {
        int r = R0 + mt*16 + lg;
#pragma unroll
        for (int nt = 0; nt < 8; nt++) {
            int c = C0 + nt*8 + lt*2;
            uint32_t coff = ((uint32_t)(c >> 5))*8192u;
            int wloc = (c & 31) >> 1;
            float b0v = __ldg(bka + c) + 1.0f, b1v = __ldg(bka + c + 1) + 1.0f;
            uint32_t h, l;
            uint32_t o0 = coff + swz(r, wloc), o1 = coff + swz(r + 8, wloc);
            split2(acc[mt][nt][0] + b0v, acc[mt][nt][1] + b1v, h, l);
            *(uint32_t*)(sm + OFF_ATH + o0) = h;
            *(uint32_t*)(sm + OFF_ATL + o0) = l;
            split2(acc[mt][nt][2] + b0v, acc[mt][nt][3] + b1v, h, l);
            *(uint32_t*)(sm + OFF_ATH + o1) = h;
            *(uint32_t*)(sm + OFF_ATL + o1) = l;
        }
    }

    // ======== Phase B: mol_e ========
    ZERO_ACC(acc);
    for (int ch = 0; ch < NCHK; ch++) {
        char* ab = sm + OFF_A + (ch & 1)*ABUF_B;
        stsA(ab, pf, tid, (float*)0, 0);
        if (ch < 7) ldgA(pf, Am, (ch+1)*CHK, tid);
        CP_WAIT0();
        __syncthreads();
        uint32_t nb = sbase + OFF_B + (((ch & 1) ^ 1))*BBUF_B;
        if (ch < 7) cpB(nb, g_WvaT_hi, g_WvaT_lo, (ch+1)*CHK, tid);
        else        cpB(nb, g_WoedT_hi, g_WoedT_lo, 0, tid);
        const char* bb = sm + OFF_B + (ch & 1)*BBUF_B;
        mma_chunk(ab, ab + 8192, bb, bb + 16384, acc, R0, C0, lane);
    }
    // epilogue B: attn = pe * (me + bva) * q * k / 16 (thread-local RMW)
    {
        const int bbase = b << 7;
#pragma unroll
        for (int mt = 0; mt < 2; mt++) {
            int r = R0 + mt*16 + lg;
#pragma unroll
            for (int nt = 0; nt < 8; nt++) {
                int c = C0 + nt*8 + lt*2;
                uint32_t coff = ((uint32_t)(c >> 5))*8192u;
                int wloc = (c & 31) >> 1;
                uint32_t o0 = coff + swz(r, wloc), o1 = coff + swz(r + 8, wloc);
                float bv0 = __ldg(bva + c), bv1 = __ldg(bva + c + 1);
                float q0 = qs[c] * 0.0625f, q1 = qs[c+1] * 0.0625f;
                float k00 = g_kT[c*ROWS_TOT + bbase + r];
                float k01 = g_kT[(c+1)*ROWS_TOT + bbase + r];
                float k10 = g_kT[c*ROWS_TOT + bbase + r + 8];
                float k11 = g_kT[(c+1)*ROWS_TOT + bbase + r + 8];
                uint32_t uh0 = *(uint32_t*)(sm + OFF_ATH + o0);
                uint32_t ul0 = *(uint32_t*)(sm + OFF_ATL + o0);
                uint32_t uh1 = *(uint32_t*)(sm + OFF_ATH + o1);
                uint32_t ul1 = *(uint32_t*)(sm + OFF_ATL + o1);
                float p00 = rec_half(uh0, ul0, 0), p01 = rec_half(uh0, ul0, 1);
                float p10 = rec_half(uh1, ul1, 0), p11 = rec_half(uh1, ul1, 1);
                float a0 = p00 * (acc[mt][nt][0] + bv0) * q0 * k00;
                float a1 = p01 * (acc[mt][nt][1] + bv1) * q1 * k01;
                float a2 = p10 * (acc[mt][nt][2] + bv0) * q0 * k10;
                float a3 = p11 * (acc[mt][nt][3] + bv1) * q1 * k11;
                uint32_t h, l;
                split2(a0, a1, h, l);
                *(uint32_t*)(sm + OFF_ATH + o0) = h;
                *(uint32_t*)(sm + OFF_ATL + o0) = l;
                split2(a2, a3, h, l);
                *(uint32_t*)(sm + OFF_ATH + o1) = h;
                *(uint32_t*)(sm + OFF_ATL + o1) = l;
            }
        }
    }

    // ======== Phase C: edge_out = attn @ Woed + boed (no A staging) ========
    ZERO_ACC(acc);
    for (int ch = 0; ch < NCHK; ch++) {
        CP_WAIT0();
        __syncthreads();
        uint32_t nb = sbase + OFF_B + (((ch & 1) ^ 1))*BBUF_B;
        if (ch < 7) cpB(nb, g_WoedT_hi, g_WoedT_lo, (ch+1)*CHK, tid);
        const char* ah = sm + OFF_ATH + ch*8192;
        const char* al = sm + OFF_ATL + ch*8192;
        const char* bb = sm + OFF_B + (ch & 1)*BBUF_B;
        mma_chunk(ah, al, bb, bb + 16384, acc, R0, C0, lane);
    }
    // epilogue C
#pragma unroll
    for (int mt = 0; mt < 2; mt++) {
        int r = R0 + mt*16 + lg;
#pragma unroll
        for (int nt = 0; nt < 8; nt++) {
            int c = C0 + nt*8 + lt*2;
            float b0v = __ldg(boed + c), b1v = __ldg(boed + c + 1);
            *(float2*)(out_edge + ((size_t)bm*NN + r)*CC + c) =
                make_float2(acc[mt][nt][0] + b0v, acc[mt][nt][1] + b1v);
            *(float2*)(out_edge + ((size_t)bm*NN + r + 8)*CC + c) =
                make_float2(acc[mt][nt][2] + b0v, acc[mt][nt][3] + b1v);
        }
    }

    // ======== softmax (2-way split over n) + node projection ========
    {
        float* red  = (float*)(sm + OFF_A);          // 512 floats
        float* red2 = (float*)(sm + OFF_A + 2048);   // 512 floats
        float* nodes = (float*)(sm + OFF_NODES);

        const int c = tid & 255, half = tid >> 8;
        const int odd = c & 1;
        const int wloc = (c & 31) >> 1;
        const char* bh = sm + OFF_ATH + ((uint32_t)(c >> 5))*8192u;
        const char* bl = sm + OFF_ATL + ((uint32_t)(c >> 5))*8192u;
        const int n0 = half*64;

        float mx = -1e30f;
#pragma unroll 4
        for (int i = 0; i < 64; i++) {
            uint32_t off = swz(n0 + i, wloc);
            float v = rec_half(*(const uint32_t*)(bh + off),
                               *(const uint32_t*)(bl + off), odd);
            mx = fmaxf(mx, v);
        }
        red[tid] = mx;
        __syncthreads();
        mx = fmaxf(red[c], red[256 + c]);

        float s = 0.f, nv = 0.f;
        const float* vb = g_v + (size_t)((b << 7) + n0)*CC + c;
#pragma unroll 4
        for (int i = 0; i < 64; i++) {
            uint32_t off = swz(n0 + i, wloc);
            float v = rec_half(*(const uint32_t*)(bh + off),
                               *(const uint32_t*)(bl + off), odd);
            float e = __expf(v - mx);
            s += e;
            nv += e * vb[(size_t)i*CC];
        }
        __syncthreads();
        red[tid] = s; red2[tid] = nv;
        __syncthreads();
        if (tid < 256)
            nodes[c] = (red2[c] + red2[256 + c]) / (red[c] + red[256 + c]);
        __syncthreads();

        // node @ Wond: 2-way split over k
        float a2 = 0.f;
        const int k0 = half*128;
#pragma unroll 4
        for (int k = 0; k < 128; k++)
            a2 += nodes[k0 + k] * Wond[(k0 + k)*CC + c];
        red[tid] = a2;
        __syncthreads();
        if (tid < 256)
            out_node[bm*CC + c] = red[c] + red[256 + c] + __ldg(bond + c);
    }
}

// ---------------- launch ----------------
extern "C" void kernel_launch(void* const* d_in, const int* in_sizes, int n_in,
                              void* d_out, int out_size)
{
    const float* mol_annot  = (const float*)d_in[0];
    const float* prot_annot = (const float*)d_in[1];
    const float* mol_adj    = (const float*)d_in[2];
    const float* prot_adj   = (const float*)d_in[3];
    const float* Wq   = (const float*)d_in[4];   const float* bq   = (const float*)d_in[5];
    const float* Wk   = (const float*)d_in[6];   const float* bk   = (const float*)d_in[7];
    const float* Wv   = (const float*)d_in[8];   const float* bv   = (const float*)d_in[9];
    const float* Wka  = (const float*)d_in[10];  const float* bka  = (const float*)d_in[11];
    const float* Wva  = (const float*)d_in[12];  const float* bva  = (const float*)d_in[13];
    const float* Wond = (const float*)d_in[14];  const float* bond = (const float*)d_in[15];
    const float* Woed = (const float*)d_in[16];  const float* boed = (const float*)d_in[17];

    float* out = (float*)d_out;
    const size_t ANNOT = (size_t)BB*NN*CC;
    const size_t ADJ   = (size_t)BB*NN*NN*CC;
    float* out_node       = out;
    float* out_prot_annot = out + ANNOT;
    float* out_edge       = out + 2*ANNOT;
    float* out_prot_adj   = out + 2*ANNOT + ADJ;

    cudaFuncSetAttribute(edge_kernel,
                         cudaFuncAttributeMaxDynamicSharedMemorySize, SMEM_BYTES);

    prep_kernel<<<120, 256>>>(Wka, Wva, Woed,
                              mol_annot, prot_annot, Wq, bq, Wk, bk, Wv, bv,
                              out_prot_annot);

    edge_kernel<<<ROWS_TOT, THREADS, SMEM_BYTES>>>(
        mol_adj, prot_adj, bka, bva, boed, bond, Wond,
        out_node, out_edge, out_prot_adj);
}

// round 7
// speedup vs baseline: 4.9353x; 1.0434x over previous
#include <cuda_runtime.h>
#include <cuda_bf16.h>
#include <stdint.h>
#include <math.h>

#define BB 8
#define NN 128
#define CC 256
#define ROWS_TOT (BB*NN)     /* 1024 */
#define CHK 32               /* K-chunk */
#define NCHK 8               /* chunks per phase */
#define THREADS 512

// ---------------- scratch ----------------
__device__ float g_q[ROWS_TOT*CC];
__device__ float g_kT[CC*ROWS_TOT];
__device__ float g_v[ROWS_TOT*CC];
__device__ __align__(16) __nv_bfloat16 g_WkaT_hi[CC*CC];
__device__ __align__(16) __nv_bfloat16 g_WkaT_lo[CC*CC];
__device__ __align__(16) __nv_bfloat16 g_WvaT_hi[CC*CC];
__device__ __align__(16) __nv_bfloat16 g_WvaT_lo[CC*CC];
__device__ __align__(16) __nv_bfloat16 g_WoedT_hi[CC*CC];
__device__ __align__(16) __nv_bfloat16 g_WoedT_lo[CC*CC];

// ---------------- helpers ----------------
__device__ __forceinline__ void mma_bf16(float acc[4],
    uint32_t a0, uint32_t a1, uint32_t a2, uint32_t a3,
    uint32_t b0, uint32_t b1)
{
    asm volatile(
        "mma.sync.aligned.m16n8k16.row.col.f32.bf16.bf16.f32 "
        "{%0,%1,%2,%3}, {%4,%5,%6,%7}, {%8,%9}, {%0,%1,%2,%3};"
        : "+f"(acc[0]), "+f"(acc[1]), "+f"(acc[2]), "+f"(acc[3])
        : "r"(a0), "r"(a1), "r"(a2), "r"(a3), "r"(b0), "r"(b1));
}

#define LDSM_X4(rg, addr) \
    asm volatile("ldmatrix.sync.aligned.m8n8.x4.shared.b16 {%0,%1,%2,%3}, [%4];" \
        : "=r"((rg)[0]), "=r"((rg)[1]), "=r"((rg)[2]), "=r"((rg)[3]) : "r"(addr))

__device__ __forceinline__ void split2(float a, float b, uint32_t& hi, uint32_t& lo) {
    __nv_bfloat16 ha = __float2bfloat16(a), hb = __float2bfloat16(b);
    __nv_bfloat162 h; h.x = ha; h.y = hb;
    hi = *reinterpret_cast<uint32_t*>(&h);
    __nv_bfloat162 l;
    l.x = __float2bfloat16(a - __bfloat162float(ha));
    l.y = __float2bfloat16(b - __bfloat162float(hb));
    lo = *reinterpret_cast<uint32_t*>(&l);
}

__device__ __forceinline__ uint32_t smem_to_u32(const void* p) {
    uint32_t a;
    asm("{ .reg .u64 t; cvta.to.shared.u64 t, %1; cvt.u32.u64 %0, t; }" : "=r"(a) : "l"(p));
    return a;
}

#define CP_ASYNC16(dst_u32, src_ptr) \
    asm volatile("cp.async.cg.shared.global [%0], [%1], 16;" \
        :: "r"(dst_u32), "l"(src_ptr) : "memory")
#define CP_COMMIT()  asm volatile("cp.async.commit_group;" ::: "memory")
#define CP_WAIT0()   asm volatile("cp.async.wait_group 0;" ::: "memory")

// Swizzle for 64-byte rows (32 bf16 = 16 words). XOR is 4-word-granular, so
// every 16-byte (4-word-aligned) block stays contiguous -> ldmatrix-compatible.
__device__ __forceinline__ uint32_t swz(int row, int w) {
    return (uint32_t)(row*64 + ((w ^ (((row >> 1) & 3) << 2)) << 2));
}

// ---------------- SMEM layout (bytes) ----------------
#define OFF_QS    0
#define OFF_NODES 1024
#define OFF_A     2048       /* 2 bufs x (hi 8K + lo 8K) = 32K; reused as reduce scratch */
#define ABUF_B    16384
#define OFF_B     34816      /* 2 bufs x (hi 16K + lo 16K) = 64K */
#define BBUF_B    32768
#define OFF_ATH   100352     /* attn hi: 8 chunks x 8K */
#define OFF_ATL   165888     /* attn lo */
#define SMEM_BYTES 231424

// ---------------- prep ----------------
__global__ __launch_bounds__(256) void prep_kernel(
    const float* __restrict__ Wka, const float* __restrict__ Wva,
    const float* __restrict__ Woed,
    const float* __restrict__ mol, const float* __restrict__ prot,
    const float* __restrict__ Wq, const float* __restrict__ bq,
    const float* __restrict__ Wk, const float* __restrict__ bk,
    const float* __restrict__ Wv, const float* __restrict__ bv,
    float* __restrict__ out_prot_annot)
{
    __shared__ float SH[8448];
    int tid = threadIdx.x;
    int bid = blockIdx.x;
    if (bid < 24) {
        int mat = bid >> 3, k0 = (bid & 7) * CHK;
        const float* W = (mat == 0) ? Wka : (mat == 1) ? Wva : Woed;
        __nv_bfloat16* GH = (mat == 0) ? g_WkaT_hi : (mat == 1) ? g_WvaT_hi : g_WoedT_hi;
        __nv_bfloat16* GL = (mat == 0) ? g_WkaT_lo : (mat == 1) ? g_WvaT_lo : g_WoedT_lo;
        for (int i = tid; i < 32*256; i += 256) {
            int kk = i >> 8, n = i & 255;
            SH[kk*257 + n] = W[(k0 + kk)*CC + n];
        }
        __syncthreads();
        int n = tid;
        uint32_t hi[16], lo[16];
#pragma unroll
        for (int j = 0; j < 16; j++)
            split2(SH[(2*j)*257 + n], SH[(2*j+1)*257 + n], hi[j], lo[j]);
        uint4* dh = (uint4*)(GH + n*CC + k0);
        uint4* dl = (uint4*)(GL + n*CC + k0);
#pragma unroll
        for (int j = 0; j < 4; j++) {
            dh[j] = make_uint4(hi[j*4], hi[j*4+1], hi[j*4+2], hi[j*4+3]);
            dl[j] = make_uint4(lo[j*4], lo[j*4+1], lo[j*4+2], lo[j*4+3]);
        }
    } else if (bid < 88) {
        float* Am = SH;
        float* Ap = SH + 4224;
        int r0 = (bid - 24) * 16;
        for (int i = tid; i < 16*CC; i += 256) {
            int r = i >> 8, c = i & 255;
            Am[i] = mol [(r0 + r)*CC + c];
            Ap[i] = prot[(r0 + r)*CC + c];
        }
        __syncthreads();
        int c = tid;
        float aq[16], ak[16], av[16];
#pragma unroll
        for (int r = 0; r < 16; r++) { aq[r]=0.f; ak[r]=0.f; av[r]=0.f; }
        for (int k = 0; k < CC; k++) {
            float wq = Wq[k*CC + c], wk = Wk[k*CC + c], wv = Wv[k*CC + c];
#pragma unroll
            for (int r = 0; r < 16; r++) {
                float am = Am[r*CC + k], ap = Ap[r*CC + k];
                aq[r] += am*wq; ak[r] += ap*wk; av[r] += am*wv;
            }
        }
        float bqv = bq[c], bkv = bk[c], bvv = bv[c];
#pragma unroll
        for (int r = 0; r < 16; r++) {
            g_q [(r0+r)*CC + c]       = aq[r] + bqv;
            g_kT[c*ROWS_TOT + r0 + r] = ak[r] + bkv;
            g_v [(r0+r)*CC + c]       = av[r] + bvv;
        }
    } else {
        const float4* src = (const float4*)prot;
        float4* dst = (float4*)out_prot_annot;
        int base = (bid - 88) * 2048;
#pragma unroll
        for (int u = 0; u < 8; u++)
            dst[base + u*256 + tid] = src[base + u*256 + tid];
    }
}

extern __shared__ char smem_raw[];

// ---------------- staging (512 threads) ----------------
__device__ __forceinline__ void ldgA(float4 pf[2], const float* __restrict__ Ag,
                                     int k0, int tid)
{
#pragma unroll
    for (int u = 0; u < 2; u++) {
        int idx = u*THREADS + tid;
        int row = idx >> 3, j = idx & 7;
        pf[u] = *(const float4*)(Ag + row*CC + k0 + j*4);
    }
}

__device__ __forceinline__ void stsA(char* ab, const float4 pf[2], int tid,
                                     float* __restrict__ outp, int k0)
{
#pragma unroll
    for (int u = 0; u < 2; u++) {
        int idx = u*THREADS + tid;
        int row = idx >> 3, j = idx & 7;
        uint32_t h01, l01, h23, l23;
        split2(pf[u].x, pf[u].y, h01, l01);
        split2(pf[u].z, pf[u].w, h23, l23);
        uint32_t boff = swz(row, j*2);
        *(uint2*)(ab + boff)        = make_uint2(h01, h23);
        *(uint2*)(ab + 8192 + boff) = make_uint2(l01, l23);
        if (outp) *(float4*)(outp + row*CC + k0 + j*4) = pf[u];
    }
}

__device__ __forceinline__ void cpB(uint32_t bb,
    const __nv_bfloat16* __restrict__ Whi, const __nv_bfloat16* __restrict__ Wlo,
    int k0, int tid)
{
#pragma unroll
    for (int u = 0; u < 2; u++) {
        int idx = u*THREADS + tid;
        int row = idx >> 2, t = idx & 3;
        uint32_t boff = swz(row, t*4);
        CP_ASYNC16(bb + boff,         Whi + row*CC + k0 + t*8);
        CP_ASYNC16(bb + 16384 + boff, Wlo + row*CC + k0 + t*8);
    }
    CP_COMMIT();
}

// MMA over staged K=32 chunk with ldmatrix fragment loads.
// Warp tile 32x64 at (R0, C0); acc[2][8][4]. smem bases are u32 shared addrs.
__device__ __forceinline__ void mma_chunk(
    uint32_t ah_b, uint32_t al_b, uint32_t bh_b, uint32_t bl_b,
    float acc[2][8][4], int R0, int C0, int lane)
{
    const int t = lane >> 3, r = lane & 7;
    const int arow = (t & 1)*8 + r, acolw = (t >> 1)*4;   // A tile order: m-lo,m-hi,k-lo,k-hi
    const int brow = (t >> 1)*8 + r, bcolw = (t & 1)*4;   // B tile order: b0,b1 then next nt
#pragma unroll
    for (int kk = 0; kk < 2; kk++) {
        const int wA = kk*8;
        uint32_t a0[4], a1[4], bh[4];
        uint32_t aoff0 = swz(R0 + arow, wA + acolw);
        uint32_t aoff1 = swz(R0 + 16 + arow, wA + acolw);
        // hi-pass: A-hi x (B-hi + B-lo)
        LDSM_X4(a0, ah_b + aoff0);
        LDSM_X4(a1, ah_b + aoff1);
#pragma unroll
        for (int ntp = 0; ntp < 4; ntp++) {
            uint32_t bl[4];
            uint32_t boff = swz(C0 + ntp*16 + brow, wA + bcolw);
            LDSM_X4(bh, bh_b + boff);
            LDSM_X4(bl, bl_b + boff);
            mma_bf16(acc[0][2*ntp],   a0[0],a0[1],a0[2],a0[3], bh[0],bh[1]);
            mma_bf16(acc[0][2*ntp],   a0[0],a0[1],a0[2],a0[3], bl[0],bl[1]);
            mma_bf16(acc[1][2*ntp],   a1[0],a1[1],a1[2],a1[3], bh[0],bh[1]);
            mma_bf16(acc[1][2*ntp],   a1[0],a1[1],a1[2],a1[3], bl[0],bl[1]);
            mma_bf16(acc[0][2*ntp+1], a0[0],a0[1],a0[2],a0[3], bh[2],bh[3]);
            mma_bf16(acc[0][2*ntp+1], a0[0],a0[1],a0[2],a0[3], bl[2],bl[3]);
            mma_bf16(acc[1][2*ntp+1], a1[0],a1[1],a1[2],a1[3], bh[2],bh[3]);
            mma_bf16(acc[1][2*ntp+1], a1[0],a1[1],a1[2],a1[3], bl[2],bl[3]);
        }
        // lo-pass: A-lo x B-hi
        LDSM_X4(a0, al_b + aoff0);
        LDSM_X4(a1, al_b + aoff1);
#pragma unroll
        for (int ntp = 0; ntp < 4; ntp++) {
            uint32_t boff = swz(C0 + ntp*16 + brow, wA + bcolw);
            LDSM_X4(bh, bh_b + boff);
            mma_bf16(acc[0][2*ntp],   a0[0],a0[1],a0[2],a0[3], bh[0],bh[1]);
            mma_bf16(acc[1][2*ntp],   a1[0],a1[1],a1[2],a1[3], bh[0],bh[1]);
            mma_bf16(acc[0][2*ntp+1], a0[0],a0[1],a0[2],a0[3], bh[2],bh[3]);
            mma_bf16(acc[1][2*ntp+1], a1[0],a1[1],a1[2],a1[3], bh[2],bh[3]);
        }
    }
}

#define ZERO_ACC(acc) \
    _Pragma("unroll") for (int mt = 0; mt < 2; mt++) \
    _Pragma("unroll") for (int nt = 0; nt < 8; nt++) \
    _Pragma("unroll") for (int i = 0; i < 4; i++) acc[mt][nt][i] = 0.f;

__device__ __forceinline__ float rec_half(uint32_t uh, uint32_t ul, int odd) {
    return odd ? (__uint_as_float(uh & 0xffff0000u) + __uint_as_float(ul & 0xffff0000u))
               : (__uint_as_float(uh << 16) + __uint_as_float(ul << 16));
}

// ---------------- fused edge kernel, one CTA per (b,m), 512 threads ---------
__global__ __launch_bounds__(THREADS, 1) void edge_kernel(
    const float* __restrict__ mol_adj, const float* __restrict__ prot_adj,
    const float* __restrict__ bka,  const float* __restrict__ bva,
    const float* __restrict__ boed, const float* __restrict__ bond,
    const float* __restrict__ Wond,
    float* __restrict__ out_node, float* __restrict__ out_edge,
    float* __restrict__ out_prot_adj)
{
    char* sm = smem_raw;
    const uint32_t sbase = smem_to_u32(sm);
    const int tid = threadIdx.x, wid = tid >> 5, lane = tid & 31;
    const int lg = lane >> 2, lt = lane & 3;
    const int bm = blockIdx.x, b = bm >> 7;
    const int R0 = (wid >> 2)*32, C0 = (wid & 3)*64;   // 4x4 warp grid

    float* qs = (float*)(sm + OFF_QS);
    const float* Ap = prot_adj + (size_t)bm*NN*CC;
    const float* Am = mol_adj  + (size_t)bm*NN*CC;
    float* outp = out_prot_adj + (size_t)bm*NN*CC;

    if (tid < 256) qs[tid] = g_q[bm*CC + tid];

    float acc[2][8][4];
    float4 pf[2];

    // prologue
    ldgA(pf, Ap, 0, tid);
    cpB(sbase + OFF_B, g_WkaT_hi, g_WkaT_lo, 0, tid);
    __syncthreads();

    // ======== Phase A: prot_e (writes prot passthrough from pf) ========
    ZERO_ACC(acc);
    for (int ch = 0; ch < NCHK; ch++) {
        char* ab = sm + OFF_A + (ch & 1)*ABUF_B;
        uint32_t abu = sbase + OFF_A + (ch & 1)*ABUF_B;
        stsA(ab, pf, tid, outp, ch*CHK);
        if (ch < 7) ldgA(pf, Ap, (ch+1)*CHK, tid);
        else        ldgA(pf, Am, 0, tid);
        CP_WAIT0();
        __syncthreads();
        uint32_t nb = sbase + OFF_B + (((ch & 1) ^ 1))*BBUF_B;
        if (ch < 7) cpB(nb, g_WkaT_hi, g_WkaT_lo, (ch+1)*CHK, tid);
        else        cpB(nb, g_WvaT_hi, g_WvaT_lo, 0, tid);
        uint32_t bbu = sbase + OFF_B + (ch & 1)*BBUF_B;
        mma_chunk(abu, abu + 8192, bbu, bbu + 16384, acc, R0, C0, lane);
    }
    // epilogue A: split(pe + bka + 1) into attn hi/lo
#pragma unroll
    for (int mt = 0; mt < 2; mt++) {
        int r = R0 + mt*16 + lg;
#pragma unroll
        for (int nt = 0; nt < 8; nt++) {
            int c = C0 + nt*8 + lt*2;
            uint32_t coff = ((uint32_t)(c >> 5))*8192u;
            int wloc = (c & 31) >> 1;
            float b0v = __ldg(bka + c) + 1.0f, b1v = __ldg(bka + c + 1) + 1.0f;
            uint32_t h, l;
            uint32_t o0 = coff + swz(r, wloc), o1 = coff + swz(r + 8, wloc);
            split2(acc[mt][nt][0] + b0v, acc[mt][nt][1] + b1v, h, l);
            *(uint32_t*)(sm + OFF_ATH + o0) = h;
            *(uint32_t*)(sm + OFF_ATL + o0) = l;
            split2(acc[mt][nt][2] + b0v, acc[mt][nt][3] + b1v, h, l);
            *(uint32_t*)(sm + OFF_ATH + o1) = h;
            *(uint32_t*)(sm + OFF_ATL + o1) = l;
        }
    }

    // ======== Phase B: mol_e ========
    ZERO_ACC(acc);
    for (int ch = 0; ch < NCHK; ch++) {
        char* ab = sm + OFF_A + (ch & 1)*ABUF_B;
        uint32_t abu = sbase + OFF_A + (ch & 1)*ABUF_B;
        stsA(ab, pf, tid, (float*)0, 0);
        if (ch < 7) ldgA(pf, Am, (ch+1)*CHK, tid);
        CP_WAIT0();
        __syncthreads();
        uint32_t nb = sbase + OFF_B + (((ch & 1) ^ 1))*BBUF_B;
        if (ch < 7) cpB(nb, g_WvaT_hi, g_WvaT_lo, (ch+1)*CHK, tid);
        else        cpB(nb, g_WoedT_hi, g_WoedT_lo, 0, tid);
        uint32_t bbu = sbase + OFF_B + (ch & 1)*BBUF_B;
        mma_chunk(abu, abu + 8192, bbu, bbu + 16384, acc, R0, C0, lane);
    }
    // epilogue B: attn = pe * (me + bva) * q * k / 16
    {
        const int bbase = b << 7;
#pragma unroll
        for (int mt = 0; mt < 2; mt++) {
            int r = R0 + mt*16 + lg;
#pragma unroll
            for (int nt = 0; nt < 8; nt++) {
                int c = C0 + nt*8 + lt*2;
                uint32_t coff = ((uint32_t)(c >> 5))*8192u;
                int wloc = (c & 31) >> 1;
                uint32_t o0 = coff + swz(r, wloc), o1 = coff + swz(r + 8, wloc);
                float bv0 = __ldg(bva + c), bv1 = __ldg(bva + c + 1);
                float q0 = qs[c] * 0.0625f, q1 = qs[c+1] * 0.0625f;
                float k00 = g_kT[c*ROWS_TOT + bbase + r];
                float k01 = g_kT[(c+1)*ROWS_TOT + bbase + r];
                float k10 = g_kT[c*ROWS_TOT + bbase + r + 8];
                float k11 = g_kT[(c+1)*ROWS_TOT + bbase + r + 8];
                uint32_t uh0 = *(uint32_t*)(sm + OFF_ATH + o0);
                uint32_t ul0 = *(uint32_t*)(sm + OFF_ATL + o0);
                uint32_t uh1 = *(uint32_t*)(sm + OFF_ATH + o1);
                uint32_t ul1 = *(uint32_t*)(sm + OFF_ATL + o1);
                float p00 = rec_half(uh0, ul0, 0), p01 = rec_half(uh0, ul0, 1);
                float p10 = rec_half(uh1, ul1, 0), p11 = rec_half(uh1, ul1, 1);
                float a0 = p00 * (acc[mt][nt][0] + bv0) * q0 * k00;
                float a1 = p01 * (acc[mt][nt][1] + bv1) * q1 * k01;
                float a2 = p10 * (acc[mt][nt][2] + bv0) * q0 * k10;
                float a3 = p11 * (acc[mt][nt][3] + bv1) * q1 * k11;
                uint32_t h, l;
                split2(a0, a1, h, l);
                *(uint32_t*)(sm + OFF_ATH + o0) = h;
                *(uint32_t*)(sm + OFF_ATL + o0) = l;
                split2(a2, a3, h, l);
                *(uint32_t*)(sm + OFF_ATH + o1) = h;
                *(uint32_t*)(sm + OFF_ATL + o1) = l;
            }
        }
    }

    // ======== Phase C: edge_out = attn @ Woed + boed (no A staging) ========
    ZERO_ACC(acc);
    for (int ch = 0; ch < NCHK; ch++) {
        CP_WAIT0();
        __syncthreads();
        uint32_t nb = sbase + OFF_B + (((ch & 1) ^ 1))*BBUF_B;
        if (ch < 7) cpB(nb, g_WoedT_hi, g_WoedT_lo, (ch+1)*CHK, tid);
        uint32_t ah = sbase + OFF_ATH + ch*8192;
        uint32_t al = sbase + OFF_ATL + ch*8192;
        uint32_t bbu = sbase + OFF_B + (ch & 1)*BBUF_B;
        mma_chunk(ah, al, bbu, bbu + 16384, acc, R0, C0, lane);
    }
    // epilogue C
#pragma unroll
    for (int mt = 0; mt < 2; mt++) {
        int r = R0 + mt*16 + lg;
#pragma unroll
        for (int nt = 0; nt < 8; nt++) {
            int c = C0 + nt*8 + lt*2;
            float b0v = __ldg(boed + c), b1v = __ldg(boed + c + 1);
            *(float2*)(out_edge + ((size_t)bm*NN + r)*CC + c) =
                make_float2(acc[mt][nt][0] + b0v, acc[mt][nt][1] + b1v);
            *(float2*)(out_edge + ((size_t)bm*NN + r + 8)*CC + c) =
                make_float2(acc[mt][nt][2] + b0v, acc[mt][nt][3] + b1v);
        }
    }

    // ======== softmax (2-way split over n) + node projection ========
    {
        float* red  = (float*)(sm + OFF_A);
        float* red2 = (float*)(sm + OFF_A + 2048);
        float* nodes = (float*)(sm + OFF_NODES);

        const int c = tid & 255, half = tid >> 8;
        const int odd = c & 1;
        const int wloc = (c & 31) >> 1;
        const char* bh = sm + OFF_ATH + ((uint32_t)(c >> 5))*8192u;
        const char* bl = sm + OFF_ATL + ((uint32_t)(c >> 5))*8192u;
        const int n0 = half*64;

        float mx = -1e30f;
#pragma unroll 4
        for (int i = 0; i < 64; i++) {
            uint32_t off = swz(n0 + i, wloc);
            float v = rec_half(*(const uint32_t*)(bh + off),
                               *(const uint32_t*)(bl + off), odd);
            mx = fmaxf(mx, v);
        }
        red[tid] = mx;
        __syncthreads();
        mx = fmaxf(red[c], red[256 + c]);

        float s = 0.f, nv = 0.f;
        const float* vb = g_v + (size_t)((b << 7) + n0)*CC + c;
#pragma unroll 4
        for (int i = 0; i < 64; i++) {
            uint32_t off = swz(n0 + i, wloc);
            float v = rec_half(*(const uint32_t*)(bh + off),
                               *(const uint32_t*)(bl + off), odd);
            float e = __expf(v - mx);
            s += e;
            nv += e * vb[(size_t)i*CC];
        }
        __syncthreads();
        red[tid] = s; red2[tid] = nv;
        __syncthreads();
        if (tid < 256)
            nodes[c] = (red2[c] + red2[256 + c]) / (red[c] + red[256 + c]);
        __syncthreads();

        float a2 = 0.f;
        const int k0 = half*128;
#pragma unroll 4
        for (int k = 0; k < 128; k++)
            a2 += nodes[k0 + k] * Wond[(k0 + k)*CC + c];
        red[tid] = a2;
        __syncthreads();
        if (tid < 256)
            out_node[bm*CC + c] = red[c] + red[256 + c] + __ldg(bond + c);
    }
}

// ---------------- launch ----------------
extern "C" void kernel_launch(void* const* d_in, const int* in_sizes, int n_in,
                              void* d_out, int out_size)
{
    const float* mol_annot  = (const float*)d_in[0];
    const float* prot_annot = (const float*)d_in[1];
    const float* mol_adj    = (const float*)d_in[2];
    const float* prot_adj   = (const float*)d_in[3];
    const float* Wq   = (const float*)d_in[4];   const float* bq   = (const float*)d_in[5];
    const float* Wk   = (const float*)d_in[6];   const float* bk   = (const float*)d_in[7];
    const float* Wv   = (const float*)d_in[8];   const float* bv   = (const float*)d_in[9];
    const float* Wka  = (const float*)d_in[10];  const float* bka  = (const float*)d_in[11];
    const float* Wva  = (const float*)d_in[12];  const float* bva  = (const float*)d_in[13];
    const float* Wond = (const float*)d_in[14];  const float* bond = (const float*)d_in[15];
    const float* Woed = (const float*)d_in[16];  const float* boed = (const float*)d_in[17];

    float* out = (float*)d_out;
    const size_t ANNOT = (size_t)BB*NN*CC;
    const size_t ADJ   = (size_t)BB*NN*NN*CC;
    float* out_node       = out;
    float* out_prot_annot = out + ANNOT;
    float* out_edge       = out + 2*ANNOT;
    float* out_prot_adj   = out + 2*ANNOT + ADJ;

    cudaFuncSetAttribute(edge_kernel,
                         cudaFuncAttributeMaxDynamicSharedMemorySize, SMEM_BYTES);

    prep_kernel<<<120, 256>>>(Wka, Wva, Woed,
                              mol_annot, prot_annot, Wq, bq, Wk, bk, Wv, bv,
                              out_prot_annot);

    edge_kernel<<<ROWS_TOT, THREADS, SMEM_BYTES>>>(
        mol_adj, prot_adj, bka, bva, boed, bond, Wond,
        out_node, out_edge, out_prot_adj);
}

// round 8
// speedup vs baseline: 5.0129x; 1.0157x over previous
#include <cuda_runtime.h>
#include <cuda_bf16.h>
#include <stdint.h>
#include <math.h>

#define BB 8
#define NN 128
#define CC 256
#define ROWS_TOT (BB*NN)     /* 1024 */
#define CHK 32               /* K-chunk */
#define NCHK 8               /* chunks per phase */
#define THREADS 512

// ---------------- scratch ----------------
__device__ float g_q[ROWS_TOT*CC];
__device__ float g_kT[CC*ROWS_TOT];
__device__ float g_v[ROWS_TOT*CC];
__device__ __align__(16) __nv_bfloat16 g_WkaT_hi[CC*CC];
__device__ __align__(16) __nv_bfloat16 g_WkaT_lo[CC*CC];
__device__ __align__(16) __nv_bfloat16 g_WvaT_hi[CC*CC];
__device__ __align__(16) __nv_bfloat16 g_WvaT_lo[CC*CC];
__device__ __align__(16) __nv_bfloat16 g_WoedT_hi[CC*CC];
__device__ __align__(16) __nv_bfloat16 g_WoedT_lo[CC*CC];

// ---------------- helpers ----------------
__device__ __forceinline__ void mma_bf16(float acc[4],
    uint32_t a0, uint32_t a1, uint32_t a2, uint32_t a3,
    uint32_t b0, uint32_t b1)
{
    asm volatile(
        "mma.sync.aligned.m16n8k16.row.col.f32.bf16.bf16.f32 "
        "{%0,%1,%2,%3}, {%4,%5,%6,%7}, {%8,%9}, {%0,%1,%2,%3};"
        : "+f"(acc[0]), "+f"(acc[1]), "+f"(acc[2]), "+f"(acc[3])
        : "r"(a0), "r"(a1), "r"(a2), "r"(a3), "r"(b0), "r"(b1));
}

#define LDSM_X4(rg, addr) \
    asm volatile("ldmatrix.sync.aligned.m8n8.x4.shared.b16 {%0,%1,%2,%3}, [%4];" \
        : "=r"((rg)[0]), "=r"((rg)[1]), "=r"((rg)[2]), "=r"((rg)[3]) : "r"(addr))

__device__ __forceinline__ void split2(float a, float b, uint32_t& hi, uint32_t& lo) {
    __nv_bfloat16 ha = __float2bfloat16(a), hb = __float2bfloat16(b);
    __nv_bfloat162 h; h.x = ha; h.y = hb;
    hi = *reinterpret_cast<uint32_t*>(&h);
    __nv_bfloat162 l;
    l.x = __float2bfloat16(a - __bfloat162float(ha));
    l.y = __float2bfloat16(b - __bfloat162float(hb));
    lo = *reinterpret_cast<uint32_t*>(&l);
}

__device__ __forceinline__ uint32_t smem_to_u32(const void* p) {
    uint32_t a;
    asm("{ .reg .u64 t; cvta.to.shared.u64 t, %1; cvt.u32.u64 %0, t; }" : "=r"(a) : "l"(p));
    return a;
}

#define CP_ASYNC16(dst_u32, src_ptr) \
    asm volatile("cp.async.cg.shared.global [%0], [%1], 16;" \
        :: "r"(dst_u32), "l"(src_ptr) : "memory")
#define CP_COMMIT()  asm volatile("cp.async.commit_group;" ::: "memory")
#define CP_WAIT0()   asm volatile("cp.async.wait_group 0;" ::: "memory")

// Swizzle for 64-byte rows (32 bf16 = 16 words). XOR is 4-word-granular, so
// every 16-byte block stays contiguous -> ldmatrix-compatible.
__device__ __forceinline__ uint32_t swz(int row, int w) {
    return (uint32_t)(row*64 + ((w ^ (((row >> 1) & 3) << 2)) << 2));
}

// ---------------- SMEM layout (bytes) ----------------
#define OFF_QS    0
#define OFF_NODES 1024
#define OFF_A     2048       /* 2 bufs x (hi 8K + lo 8K) = 32K; reused as reduce scratch */
#define ABUF_B    16384
#define OFF_B     34816      /* 2 bufs x (hi 16K + lo 16K) = 64K */
#define BBUF_B    32768
#define OFF_ATH   100352     /* attn hi: 8 chunks x 8K */
#define OFF_ATL   165888     /* attn lo */
#define SMEM_BYTES 231424

// ---------------- prep ----------------
__global__ __launch_bounds__(256) void prep_kernel(
    const float* __restrict__ Wka, const float* __restrict__ Wva,
    const float* __restrict__ Woed,
    const float* __restrict__ mol, const float* __restrict__ prot,
    const float* __restrict__ Wq, const float* __restrict__ bq,
    const float* __restrict__ Wk, const float* __restrict__ bk,
    const float* __restrict__ Wv, const float* __restrict__ bv,
    float* __restrict__ out_prot_annot)
{
    __shared__ float SH[8448];
    int tid = threadIdx.x;
    int bid = blockIdx.x;
    if (bid < 24) {
        int mat = bid >> 3, k0 = (bid & 7) * CHK;
        const float* W = (mat == 0) ? Wka : (mat == 1) ? Wva : Woed;
        __nv_bfloat16* GH = (mat == 0) ? g_WkaT_hi : (mat == 1) ? g_WvaT_hi : g_WoedT_hi;
        __nv_bfloat16* GL = (mat == 0) ? g_WkaT_lo : (mat == 1) ? g_WvaT_lo : g_WoedT_lo;
        for (int i = tid; i < 32*256; i += 256) {
            int kk = i >> 8, n = i & 255;
            SH[kk*257 + n] = W[(k0 + kk)*CC + n];
        }
        __syncthreads();
        int n = tid;
        uint32_t hi[16], lo[16];
#pragma unroll
        for (int j = 0; j < 16; j++)
            split2(SH[(2*j)*257 + n], SH[(2*j+1)*257 + n], hi[j], lo[j]);
        uint4* dh = (uint4*)(GH + n*CC + k0);
        uint4* dl = (uint4*)(GL + n*CC + k0);
#pragma unroll
        for (int j = 0; j < 4; j++) {
            dh[j] = make_uint4(hi[j*4], hi[j*4+1], hi[j*4+2], hi[j*4+3]);
            dl[j] = make_uint4(lo[j*4], lo[j*4+1], lo[j*4+2], lo[j*4+3]);
        }
    } else if (bid < 88) {
        float* Am = SH;
        float* Ap = SH + 4224;
        int r0 = (bid - 24) * 16;
        for (int i = tid; i < 16*CC; i += 256) {
            int r = i >> 8, c = i & 255;
            Am[i] = mol [(r0 + r)*CC + c];
            Ap[i] = prot[(r0 + r)*CC + c];
        }
        __syncthreads();
        int c = tid;
        float aq[16], ak[16], av[16];
#pragma unroll
        for (int r = 0; r < 16; r++) { aq[r]=0.f; ak[r]=0.f; av[r]=0.f; }
        for (int k = 0; k < CC; k++) {
            float wq = Wq[k*CC + c], wk = Wk[k*CC + c], wv = Wv[k*CC + c];
#pragma unroll
            for (int r = 0; r < 16; r++) {
                float am = Am[r*CC + k], ap = Ap[r*CC + k];
                aq[r] += am*wq; ak[r] += ap*wk; av[r] += am*wv;
            }
        }
        float bqv = bq[c], bkv = bk[c], bvv = bv[c];
#pragma unroll
        for (int r = 0; r < 16; r++) {
            g_q [(r0+r)*CC + c]       = aq[r] + bqv;
            g_kT[c*ROWS_TOT + r0 + r] = ak[r] + bkv;
            g_v [(r0+r)*CC + c]       = av[r] + bvv;
        }
    } else {
        const float4* src = (const float4*)prot;
        float4* dst = (float4*)out_prot_annot;
        int base = (bid - 88) * 2048;
#pragma unroll
        for (int u = 0; u < 8; u++)
            dst[base + u*256 + tid] = src[base + u*256 + tid];
    }
}

extern __shared__ char smem_raw[];

// ---------------- staging (512 threads) ----------------
__device__ __forceinline__ void ldgA(float4 pf[2], const float* __restrict__ Ag,
                                     int k0, int tid)
{
#pragma unroll
    for (int u = 0; u < 2; u++) {
        int idx = u*THREADS + tid;
        int row = idx >> 3, j = idx & 7;
        pf[u] = *(const float4*)(Ag + row*CC + k0 + j*4);
    }
}

__device__ __forceinline__ void stsA(char* ab, const float4 pf[2], int tid,
                                     float* __restrict__ outp, int k0)
{
#pragma unroll
    for (int u = 0; u < 2; u++) {
        int idx = u*THREADS + tid;
        int row = idx >> 3, j = idx & 7;
        uint32_t h01, l01, h23, l23;
        split2(pf[u].x, pf[u].y, h01, l01);
        split2(pf[u].z, pf[u].w, h23, l23);
        uint32_t boff = swz(row, j*2);
        *(uint2*)(ab + boff)        = make_uint2(h01, h23);
        *(uint2*)(ab + 8192 + boff) = make_uint2(l01, l23);
        if (outp) *(float4*)(outp + row*CC + k0 + j*4) = pf[u];
    }
}

__device__ __forceinline__ void cpB(uint32_t bb,
    const __nv_bfloat16* __restrict__ Whi, const __nv_bfloat16* __restrict__ Wlo,
    int k0, int tid)
{
#pragma unroll
    for (int u = 0; u < 2; u++) {
        int idx = u*THREADS + tid;
        int row = idx >> 2, t = idx & 3;
        uint32_t boff = swz(row, t*4);
        CP_ASYNC16(bb + boff,         Whi + row*CC + k0 + t*8);
        CP_ASYNC16(bb + 16384 + boff, Wlo + row*CC + k0 + t*8);
    }
    CP_COMMIT();
}

// MMA over staged K=32 chunk with ldmatrix fragment loads.
// Warp tile 32x64 at (R0, C0); acc[2][8][4].
// MMA issue order arranged so consecutive HMMAs never target the same
// accumulator (distance >= 4 instructions) -- breaks RAW latency chains.
// Per-accumulator addition order (bh, bl, then lo-pass bh) is unchanged.
__device__ __forceinline__ void mma_chunk(
    uint32_t ah_b, uint32_t al_b, uint32_t bh_b, uint32_t bl_b,
    float acc[2][8][4], int R0, int C0, int lane)
{
    const int t = lane >> 3, r = lane & 7;
    const int arow = (t & 1)*8 + r, acolw = (t >> 1)*4;
    const int brow = (t >> 1)*8 + r, bcolw = (t & 1)*4;
#pragma unroll
    for (int kk = 0; kk < 2; kk++) {
        const int wA = kk*8;
        uint32_t a0[4], a1[4], bh[4];
        uint32_t aoff0 = swz(R0 + arow, wA + acolw);
        uint32_t aoff1 = swz(R0 + 16 + arow, wA + acolw);
        // hi-pass: A-hi x (B-hi, then B-lo) -- 4 distinct accs per group
        LDSM_X4(a0, ah_b + aoff0);
        LDSM_X4(a1, ah_b + aoff1);
#pragma unroll
        for (int ntp = 0; ntp < 4; ntp++) {
            uint32_t bl[4];
            uint32_t boff = swz(C0 + ntp*16 + brow, wA + bcolw);
            LDSM_X4(bh, bh_b + boff);
            LDSM_X4(bl, bl_b + boff);
            mma_bf16(acc[0][2*ntp],   a0[0],a0[1],a0[2],a0[3], bh[0],bh[1]);
            mma_bf16(acc[1][2*ntp],   a1[0],a1[1],a1[2],a1[3], bh[0],bh[1]);
            mma_bf16(acc[0][2*ntp+1], a0[0],a0[1],a0[2],a0[3], bh[2],bh[3]);
            mma_bf16(acc[1][2*ntp+1], a1[0],a1[1],a1[2],a1[3], bh[2],bh[3]);
            mma_bf16(acc[0][2*ntp],   a0[0],a0[1],a0[2],a0[3], bl[0],bl[1]);
            mma_bf16(acc[1][2*ntp],   a1[0],a1[1],a1[2],a1[3], bl[0],bl[1]);
            mma_bf16(acc[0][2*ntp+1], a0[0],a0[1],a0[2],a0[3], bl[2],bl[3]);
            mma_bf16(acc[1][2*ntp+1], a1[0],a1[1],a1[2],a1[3], bl[2],bl[3]);
        }
        // lo-pass: A-lo x B-hi -- 4 distinct accs per group
        LDSM_X4(a0, al_b + aoff0);
        LDSM_X4(a1, al_b + aoff1);
#pragma unroll
        for (int ntp = 0; ntp < 4; ntp++) {
            uint32_t boff = swz(C0 + ntp*16 + brow, wA + bcolw);
            LDSM_X4(bh, bh_b + boff);
            mma_bf16(acc[0][2*ntp],   a0[0],a0[1],a0[2],a0[3], bh[0],bh[1]);
            mma_bf16(acc[1][2*ntp],   a1[0],a1[1],a1[2],a1[3], bh[0],bh[1]);
            mma_bf16(acc[0][2*ntp+1], a0[0],a0[1],a0[2],a0[3], bh[2],bh[3]);
            mma_bf16(acc[1][2*ntp+1], a1[0],a1[1],a1[2],a1[3], bh[2],bh[3]);
        }
    }
}

#define ZERO_ACC(acc) \
    _Pragma("unroll") for (int mt = 0; mt < 2; mt++) \
    _Pragma("unroll") for (int nt = 0; nt < 8; nt++) \
    _Pragma("unroll") for (int i = 0; i < 4; i++) acc[mt][nt][i] = 0.f;

__device__ __forceinline__ float rec_half(uint32_t uh, uint32_t ul, int odd) {
    return odd ? (__uint_as_float(uh & 0xffff0000u) + __uint_as_float(ul & 0xffff0000u))
               : (__uint_as_float(uh << 16) + __uint_as_float(ul << 16));
}

// ---------------- fused edge kernel, one CTA per (b,m), 512 threads ---------
__global__ __launch_bounds__(THREADS, 1) void edge_kernel(
    const float* __restrict__ mol_adj, const float* __restrict__ prot_adj,
    const float* __restrict__ bka,  const float* __restrict__ bva,
    const float* __restrict__ boed, const float* __restrict__ bond,
    const float* __restrict__ Wond,
    float* __restrict__ out_node, float* __restrict__ out_edge,
    float* __restrict__ out_prot_adj)
{
    char* sm = smem_raw;
    const uint32_t sbase = smem_to_u32(sm);
    const int tid = threadIdx.x, wid = tid >> 5, lane = tid & 31;
    const int lg = lane >> 2, lt = lane & 3;
    const int bm = blockIdx.x, b = bm >> 7;
    const int R0 = (wid >> 2)*32, C0 = (wid & 3)*64;   // 4x4 warp grid

    float* qs = (float*)(sm + OFF_QS);
    const float* Ap = prot_adj + (size_t)bm*NN*CC;
    const float* Am = mol_adj  + (size_t)bm*NN*CC;
    float* outp = out_prot_adj + (size_t)bm*NN*CC;

    if (tid < 256) qs[tid] = g_q[bm*CC + tid];

    float acc[2][8][4];
    float4 pf[2];

    // prologue
    ldgA(pf, Ap, 0, tid);
    cpB(sbase + OFF_B, g_WkaT_hi, g_WkaT_lo, 0, tid);
    __syncthreads();

    // ======== Phase A: prot_e (writes prot passthrough from pf) ========
    ZERO_ACC(acc);
    for (int ch = 0; ch < NCHK; ch++) {
        char* ab = sm + OFF_A + (ch & 1)*ABUF_B;
        uint32_t abu = sbase + OFF_A + (ch & 1)*ABUF_B;
        stsA(ab, pf, tid, outp, ch*CHK);
        if (ch < 7) ldgA(pf, Ap, (ch+1)*CHK, tid);
        else        ldgA(pf, Am, 0, tid);
        CP_WAIT0();
        __syncthreads();
        uint32_t nb = sbase + OFF_B + (((ch & 1) ^ 1))*BBUF_B;
        if (ch < 7) cpB(nb, g_WkaT_hi, g_WkaT_lo, (ch+1)*CHK, tid);
        else        cpB(nb, g_WvaT_hi, g_WvaT_lo, 0, tid);
        uint32_t bbu = sbase + OFF_B + (ch & 1)*BBUF_B;
        mma_chunk(abu, abu + 8192, bbu, bbu + 16384, acc, R0, C0, lane);
    }
    // epilogue A: split(pe + bka + 1) into attn hi/lo
#pragma unroll
    for (int mt = 0; mt < 2; mt++) {
        int r = R0 + mt*16 + lg;
#pragma unroll
        for (int nt = 0; nt < 8; nt++) {
            int c = C0 + nt*8 + lt*2;
            uint32_t coff = ((uint32_t)(c >> 5))*8192u;
            int wloc = (c & 31) >> 1;
            float b0v = __ldg(bka + c) + 1.0f, b1v = __ldg(bka + c + 1) + 1.0f;
            uint32_t h, l;
            uint32_t o0 = coff + swz(r, wloc), o1 = coff + swz(r + 8, wloc);
            split2(acc[mt][nt][0] + b0v, acc[mt][nt][1] + b1v, h, l);
            *(uint32_t*)(sm + OFF_ATH + o0) = h;
            *(uint32_t*)(sm + OFF_ATL + o0) = l;
            split2(acc[mt][nt][2] + b0v, acc[mt][nt][3] + b1v, h, l);
            *(uint32_t*)(sm + OFF_ATH + o1) = h;
            *(uint32_t*)(sm + OFF_ATL + o1) = l;
        }
    }

    // ======== Phase B: mol_e ========
    ZERO_ACC(acc);
    for (int ch = 0; ch < NCHK; ch++) {
        char* ab = sm + OFF_A + (ch & 1)*ABUF_B;
        uint32_t abu = sbase + OFF_A + (ch & 1)*ABUF_B;
        stsA(ab, pf, tid, (float*)0, 0);
        if (ch < 7) ldgA(pf, Am, (ch+1)*CHK, tid);
        CP_WAIT0();
        __syncthreads();
        uint32_t nb = sbase + OFF_B + (((ch & 1) ^ 1))*BBUF_B;
        if (ch < 7) cpB(nb, g_WvaT_hi, g_WvaT_lo, (ch+1)*CHK, tid);
        else        cpB(nb, g_WoedT_hi, g_WoedT_lo, 0, tid);
        uint32_t bbu = sbase + OFF_B + (ch & 1)*BBUF_B;
        mma_chunk(abu, abu + 8192, bbu, bbu + 16384, acc, R0, C0, lane);
    }
    // epilogue B: attn = pe * (me + bva) * q * k / 16
    {
        const int bbase = b << 7;
#pragma unroll
        for (int mt = 0; mt < 2; mt++) {
            int r = R0 + mt*16 + lg;
#pragma unroll
            for (int nt = 0; nt < 8; nt++) {
                int c = C0 + nt*8 + lt*2;
                uint32_t coff = ((uint32_t)(c >> 5))*8192u;
                int wloc = (c & 31) >> 1;
                uint32_t o0 = coff + swz(r, wloc), o1 = coff + swz(r + 8, wloc);
                float bv0 = __ldg(bva + c), bv1 = __ldg(bva + c + 1);
                float q0 = qs[c] * 0.0625f, q1 = qs[c+1] * 0.0625f;
                float k00 = g_kT[c*ROWS_TOT + bbase + r];
                float k01 = g_kT[(c+1)*ROWS_TOT + bbase + r];
                float k10 = g_kT[c*ROWS_TOT + bbase + r + 8];
                float k11 = g_kT[(c+1)*ROWS_TOT + bbase + r + 8];
                uint32_t uh0 = *(uint32_t*)(sm + OFF_ATH + o0);
                uint32_t ul0 = *(uint32_t*)(sm + OFF_ATL + o0);
                uint32_t uh1 = *(uint32_t*)(sm + OFF_ATH + o1);
                uint32_t ul1 = *(uint32_t*)(sm + OFF_ATL + o1);
                float p00 = rec_half(uh0, ul0, 0), p01 = rec_half(uh0, ul0, 1);
                float p10 = rec_half(uh1, ul1, 0), p11 = rec_half(uh1, ul1, 1);
                float a0 = p00 * (acc[mt][nt][0] + bv0) * q0 * k00;
                float a1 = p01 * (acc[mt][nt][1] + bv1) * q1 * k01;
                float a2 = p10 * (acc[mt][nt][2] + bv0) * q0 * k10;
                float a3 = p11 * (acc[mt][nt][3] + bv1) * q1 * k11;
                uint32_t h, l;
                split2(a0, a1, h, l);
                *(uint32_t*)(sm + OFF_ATH + o0) = h;
                *(uint32_t*)(sm + OFF_ATL + o0) = l;
                split2(a2, a3, h, l);
                *(uint32_t*)(sm + OFF_ATH + o1) = h;
                *(uint32_t*)(sm + OFF_ATL + o1) = l;
            }
        }
    }

    // ======== Phase C: edge_out = attn @ Woed + boed (no A staging) ========
    ZERO_ACC(acc);
    for (int ch = 0; ch < NCHK; ch++) {
        CP_WAIT0();
        __syncthreads();
        uint32_t nb = sbase + OFF_B + (((ch & 1) ^ 1))*BBUF_B;
        if (ch < 7) cpB(nb, g_WoedT_hi, g_WoedT_lo, (ch+1)*CHK, tid);
        uint32_t ah = sbase + OFF_ATH + ch*8192;
        uint32_t al = sbase + OFF_ATL + ch*8192;
        uint32_t bbu = sbase + OFF_B + (ch & 1)*BBUF_B;
        mma_chunk(ah, al, bbu, bbu + 16384, acc, R0, C0, lane);
    }
    // epilogue C
#pragma unroll
    for (int mt = 0; mt < 2; mt++) {
        int r = R0 + mt*16 + lg;
#pragma unroll
        for (int nt = 0; nt < 8; nt++) {
            int c = C0 + nt*8 + lt*2;
            float b0v = __ldg(boed + c), b1v = __ldg(boed + c + 1);
            *(float2*)(out_edge + ((size_t)bm*NN + r)*CC + c) =
                make_float2(acc[mt][nt][0] + b0v, acc[mt][nt][1] + b1v);
            *(float2*)(out_edge + ((size_t)bm*NN + r + 8)*CC + c) =
                make_float2(acc[mt][nt][2] + b0v, acc[mt][nt][3] + b1v);
        }
    }

    // ======== softmax (2-way split over n) + node projection ========
    {
        float* red  = (float*)(sm + OFF_A);
        float* red2 = (float*)(sm + OFF_A + 2048);
        float* nodes = (float*)(sm + OFF_NODES);

        const int c = tid & 255, half = tid >> 8;
        const int odd = c & 1;
        const int wloc = (c & 31) >> 1;
        const char* bh = sm + OFF_ATH + ((uint32_t)(c >> 5))*8192u;
        const char* bl = sm + OFF_ATL + ((uint32_t)(c >> 5))*8192u;
        const int n0 = half*64;

        float mx = -1e30f;
#pragma unroll 4
        for (int i = 0; i < 64; i++) {
            uint32_t off = swz(n0 + i, wloc);
            float v = rec_half(*(const uint32_t*)(bh + off),
                               *(const uint32_t*)(bl + off), odd);
            mx = fmaxf(mx, v);
        }
        red[tid] = mx;
        __syncthreads();
        mx = fmaxf(red[c], red[256 + c]);

        float s = 0.f, nv = 0.f;
        const float* vb = g_v + (size_t)((b << 7) + n0)*CC + c;
#pragma unroll 4
        for (int i = 0; i < 64; i++) {
            uint32_t off = swz(n0 + i, wloc);
            float v = rec_half(*(const uint32_t*)(bh + off),
                               *(const uint32_t*)(bl + off), odd);
            float e = __expf(v - mx);
            s += e;
            nv += e * vb[(size_t)i*CC];
        }
        __syncthreads();
        red[tid] = s; red2[tid] = nv;
        __syncthreads();
        if (tid < 256)
            nodes[c] = (red2[c] + red2[256 + c]) / (red[c] + red[256 + c]);
        __syncthreads();

        float a2 = 0.f;
        const int k0 = half*128;
#pragma unroll 4
        for (int k = 0; k < 128; k++)
            a2 += nodes[k0 + k] * Wond[(k0 + k)*CC + c];
        red[tid] = a2;
        __syncthreads();
        if (tid < 256)
            out_node[bm*CC + c] = red[c] + red[256 + c] + __ldg(bond + c);
    }
}

// ---------------- launch ----------------
extern "C" void kernel_launch(void* const* d_in, const int* in_sizes, int n_in,
                              void* d_out, int out_size)
{
    const float* mol_annot  = (const float*)d_in[0];
    const float* prot_annot = (const float*)d_in[1];
    const float* mol_adj    = (const float*)d_in[2];
    const float* prot_adj   = (const float*)d_in[3];
    const float* Wq   = (const float*)d_in[4];   const float* bq   = (const float*)d_in[5];
    const float* Wk   = (const float*)d_in[6];   const float* bk   = (const float*)d_in[7];
    const float* Wv   = (const float*)d_in[8];   const float* bv   = (const float*)d_in[9];
    const float* Wka  = (const float*)d_in[10];  const float* bka  = (const float*)d_in[11];
    const float* Wva  = (const float*)d_in[12];  const float* bva  = (const float*)d_in[13];
    const float* Wond = (const float*)d_in[14];  const float* bond = (const float*)d_in[15];
    const float* Woed = (const float*)d_in[16];  const float* boed = (const float*)d_in[17];

    float* out = (float*)d_out;
    const size_t ANNOT = (size_t)BB*NN*CC;
    const size_t ADJ   = (size_t)BB*NN*NN*CC;
    float* out_node       = out;
    float* out_prot_annot = out + ANNOT;
    float* out_edge       = out + 2*ANNOT;
    float* out_prot_adj   = out + 2*ANNOT + ADJ;

    cudaFuncSetAttribute(edge_kernel,
                         cudaFuncAttributeMaxDynamicSharedMemorySize, SMEM_BYTES);

    prep_kernel<<<120, 256>>>(Wka, Wva, Woed,
                              mol_annot, prot_annot, Wq, bq, Wk, bk, Wv, bv,
                              out_prot_annot);

    edge_kernel<<<ROWS_TOT, THREADS, SMEM_BYTES>>>(
        mol_adj, prot_adj, bka, bva, boed, bond, Wond,
        out_node, out_edge, out_prot_adj);
}

// round 9
// speedup vs baseline: 6.0477x; 1.2064x over previous
#include <cuda_runtime.h>
#include <cuda_fp16.h>
#include <stdint.h>
#include <math.h>

#define BB 8
#define NN 128
#define CC 256
#define ROWS_TOT (BB*NN)     /* 1024 */
#define CHK 32               /* K-chunk */
#define NCHK 8               /* chunks per phase */
#define THREADS 512

// ---------------- scratch ----------------
__device__ float g_q[ROWS_TOT*CC];
__device__ float g_kT[CC*ROWS_TOT];
__device__ float g_v[ROWS_TOT*CC];
__device__ __align__(16) __half g_WkaT[CC*CC];   // W^T, single fp16
__device__ __align__(16) __half g_WvaT[CC*CC];
__device__ __align__(16) __half g_WoedT[CC*CC];

// ---------------- helpers ----------------
__device__ __forceinline__ void mma_f16(float acc[4],
    uint32_t a0, uint32_t a1, uint32_t a2, uint32_t a3,
    uint32_t b0, uint32_t b1)
{
    asm volatile(
        "mma.sync.aligned.m16n8k16.row.col.f32.f16.f16.f32 "
        "{%0,%1,%2,%3}, {%4,%5,%6,%7}, {%8,%9}, {%0,%1,%2,%3};"
        : "+f"(acc[0]), "+f"(acc[1]), "+f"(acc[2]), "+f"(acc[3])
        : "r"(a0), "r"(a1), "r"(a2), "r"(a3), "r"(b0), "r"(b1));
}

#define LDSM_X4(rg, addr) \
    asm volatile("ldmatrix.sync.aligned.m8n8.x4.shared.b16 {%0,%1,%2,%3}, [%4];" \
        : "=r"((rg)[0]), "=r"((rg)[1]), "=r"((rg)[2]), "=r"((rg)[3]) : "r"(addr))

// fp32 -> fp16 hi/lo split, two values packed per word
__device__ __forceinline__ void split2h(float a, float b, uint32_t& hi, uint32_t& lo) {
    __half ha = __float2half_rn(a), hb = __float2half_rn(b);
    hi = ((uint32_t)__half_as_ushort(hb) << 16) | __half_as_ushort(ha);
    __half la = __float2half_rn(a - __half2float(ha));
    __half lb = __float2half_rn(b - __half2float(hb));
    lo = ((uint32_t)__half_as_ushort(lb) << 16) | __half_as_ushort(la);
}

__device__ __forceinline__ float rec_h(uint32_t uh, uint32_t ul, int odd) {
    unsigned short sh = odd ? (unsigned short)(uh >> 16) : (unsigned short)(uh & 0xffff);
    unsigned short sl = odd ? (unsigned short)(ul >> 16) : (unsigned short)(ul & 0xffff);
    return __half2float(__ushort_as_half(sh)) + __half2float(__ushort_as_half(sl));
}

__device__ __forceinline__ uint32_t smem_to_u32(const void* p) {
    uint32_t a;
    asm("{ .reg .u64 t; cvta.to.shared.u64 t, %1; cvt.u32.u64 %0, t; }" : "=r"(a) : "l"(p));
    return a;
}

#define CP_ASYNC16(dst_u32, src_ptr) \
    asm volatile("cp.async.cg.shared.global [%0], [%1], 16;" \
        :: "r"(dst_u32), "l"(src_ptr) : "memory")
#define CP_COMMIT()  asm volatile("cp.async.commit_group;" ::: "memory")
#define CP_WAIT0()   asm volatile("cp.async.wait_group 0;" ::: "memory")

// Swizzle for 64-byte rows (32 fp16 = 16 words). XOR is 4-word-granular:
// every 16-byte block stays contiguous -> ldmatrix-compatible.
__device__ __forceinline__ uint32_t swz(int row, int w) {
    return (uint32_t)(row*64 + ((w ^ (((row >> 1) & 3) << 2)) << 2));
}

// ---------------- SMEM layout (bytes) ----------------
#define OFF_QS    0
#define OFF_NODES 1024
#define OFF_A     2048       /* 2 bufs x (hi 8K + lo 8K) = 32K; reused as reduce scratch */
#define ABUF_B    16384
#define OFF_B     34816      /* 2 bufs x 16K = 32K (single fp16 weights) */
#define BBUF_B    16384
#define OFF_ATH   67584      /* attn hi: 8 chunks x 8K = 64K */
#define OFF_ATL   133120     /* attn lo: 64K */
#define SMEM_BYTES 198656

// ---------------- prep: weight transpose (fp16) + qkv + prot_annot copy -----
__global__ __launch_bounds__(256) void prep_kernel(
    const float* __restrict__ Wka, const float* __restrict__ Wva,
    const float* __restrict__ Woed,
    const float* __restrict__ mol, const float* __restrict__ prot,
    const float* __restrict__ Wq, const float* __restrict__ bq,
    const float* __restrict__ Wk, const float* __restrict__ bk,
    const float* __restrict__ Wv, const float* __restrict__ bv,
    float* __restrict__ out_prot_annot)
{
    __shared__ float SH[8448];
    int tid = threadIdx.x;
    int bid = blockIdx.x;
    if (bid < 24) {
        int mat = bid >> 3, k0 = (bid & 7) * CHK;
        const float* W = (mat == 0) ? Wka : (mat == 1) ? Wva : Woed;
        __half* G = (mat == 0) ? g_WkaT : (mat == 1) ? g_WvaT : g_WoedT;
        for (int i = tid; i < 32*256; i += 256) {
            int kk = i >> 8, n = i & 255;
            SH[kk*257 + n] = W[(k0 + kk)*CC + n];
        }
        __syncthreads();
        int n = tid;
        uint32_t w[16];
#pragma unroll
        for (int j = 0; j < 16; j++) {
            __half h0 = __float2half_rn(SH[(2*j)*257 + n]);
            __half h1 = __float2half_rn(SH[(2*j+1)*257 + n]);
            w[j] = ((uint32_t)__half_as_ushort(h1) << 16) | __half_as_ushort(h0);
        }
        uint4* d = (uint4*)(G + n*CC + k0);
#pragma unroll
        for (int j = 0; j < 4; j++)
            d[j] = make_uint4(w[j*4], w[j*4+1], w[j*4+2], w[j*4+3]);
    } else if (bid < 88) {
        float* Am = SH;
        float* Ap = SH + 4224;
        int r0 = (bid - 24) * 16;
        for (int i = tid; i < 16*CC; i += 256) {
            int r = i >> 8, c = i & 255;
            Am[i] = mol [(r0 + r)*CC + c];
            Ap[i] = prot[(r0 + r)*CC + c];
        }
        __syncthreads();
        int c = tid;
        float aq[16], ak[16], av[16];
#pragma unroll
        for (int r = 0; r < 16; r++) { aq[r]=0.f; ak[r]=0.f; av[r]=0.f; }
        for (int k = 0; k < CC; k++) {
            float wq = Wq[k*CC + c], wk = Wk[k*CC + c], wv = Wv[k*CC + c];
#pragma unroll
            for (int r = 0; r < 16; r++) {
                float am = Am[r*CC + k], ap = Ap[r*CC + k];
                aq[r] += am*wq; ak[r] += ap*wk; av[r] += am*wv;
            }
        }
        float bqv = bq[c], bkv = bk[c], bvv = bv[c];
#pragma unroll
        for (int r = 0; r < 16; r++) {
            g_q [(r0+r)*CC + c]       = aq[r] + bqv;
            g_kT[c*ROWS_TOT + r0 + r] = ak[r] + bkv;
            g_v [(r0+r)*CC + c]       = av[r] + bvv;
        }
    } else {
        const float4* src = (const float4*)prot;
        float4* dst = (float4*)out_prot_annot;
        int base = (bid - 88) * 2048;
#pragma unroll
        for (int u = 0; u < 8; u++)
            dst[base + u*256 + tid] = src[base + u*256 + tid];
    }
}

extern __shared__ char smem_raw[];

// ---------------- staging (512 threads) ----------------
__device__ __forceinline__ void ldgA(float4 pf[2], const float* __restrict__ Ag,
                                     int k0, int tid)
{
#pragma unroll
    for (int u = 0; u < 2; u++) {
        int idx = u*THREADS + tid;
        int row = idx >> 3, j = idx & 7;
        pf[u] = *(const float4*)(Ag + row*CC + k0 + j*4);
    }
}

__device__ __forceinline__ void stsA(char* ab, const float4 pf[2], int tid,
                                     float* __restrict__ outp, int k0)
{
#pragma unroll
    for (int u = 0; u < 2; u++) {
        int idx = u*THREADS + tid;
        int row = idx >> 3, j = idx & 7;
        uint32_t h01, l01, h23, l23;
        split2h(pf[u].x, pf[u].y, h01, l01);
        split2h(pf[u].z, pf[u].w, h23, l23);
        uint32_t boff = swz(row, j*2);
        *(uint2*)(ab + boff)        = make_uint2(h01, h23);
        *(uint2*)(ab + 8192 + boff) = make_uint2(l01, l23);
        if (outp) *(float4*)(outp + row*CC + k0 + j*4) = pf[u];
    }
}

// Weight chunk: single fp16, 16KB (256 rows x 32 halves), 2 cp.async/thread.
__device__ __forceinline__ void cpB(uint32_t bb,
    const __half* __restrict__ W, int k0, int tid)
{
#pragma unroll
    for (int u = 0; u < 2; u++) {
        int idx = u*THREADS + tid;
        int row = idx >> 2, t = idx & 3;
        CP_ASYNC16(bb + swz(row, t*4), W + row*CC + k0 + t*8);
    }
    CP_COMMIT();
}

// MMA over staged K=32 chunk; A fp16 hi/lo (2-term), B fp16 single.
// Warp tile 32x64 at (R0, C0); acc[2][8][4]. 64 MMAs + 12 LDSM_X4 per chunk.
__device__ __forceinline__ void mma_chunk(
    uint32_t ah_b, uint32_t al_b, uint32_t b_b,
    float acc[2][8][4], int R0, int C0, int lane)
{
    const int t = lane >> 3, r = lane & 7;
    const int arow = (t & 1)*8 + r, acolw = (t >> 1)*4;
    const int brow = (t >> 1)*8 + r, bcolw = (t & 1)*4;
#pragma unroll
    for (int kk = 0; kk < 2; kk++) {
        const int wA = kk*8;
        uint32_t a0h[4], a1h[4], a0l[4], a1l[4], b0[4], b1[4];
        uint32_t aoff0 = swz(R0 + arow, wA + acolw);
        uint32_t aoff1 = swz(R0 + 16 + arow, wA + acolw);
        LDSM_X4(a0h, ah_b + aoff0);
        LDSM_X4(a1h, ah_b + aoff1);
        LDSM_X4(a0l, al_b + aoff0);
        LDSM_X4(a1l, al_b + aoff1);
        LDSM_X4(b0, b_b + swz(C0 + brow, wA + bcolw));
#pragma unroll
        for (int ntp = 0; ntp < 4; ntp++) {
            uint32_t* bc = (ntp & 1) ? b1 : b0;
            uint32_t* bn = (ntp & 1) ? b0 : b1;
            if (ntp < 3) LDSM_X4(bn, b_b + swz(C0 + (ntp+1)*16 + brow, wA + bcolw));
            mma_f16(acc[0][2*ntp],   a0h[0],a0h[1],a0h[2],a0h[3], bc[0],bc[1]);
            mma_f16(acc[1][2*ntp],   a1h[0],a1h[1],a1h[2],a1h[3], bc[0],bc[1]);
            mma_f16(acc[0][2*ntp+1], a0h[0],a0h[1],a0h[2],a0h[3], bc[2],bc[3]);
            mma_f16(acc[1][2*ntp+1], a1h[0],a1h[1],a1h[2],a1h[3], bc[2],bc[3]);
            mma_f16(acc[0][2*ntp],   a0l[0],a0l[1],a0l[2],a0l[3], bc[0],bc[1]);
            mma_f16(acc[1][2*ntp],   a1l[0],a1l[1],a1l[2],a1l[3], bc[0],bc[1]);
            mma_f16(acc[0][2*ntp+1], a0l[0],a0l[1],a0l[2],a0l[3], bc[2],bc[3]);
            mma_f16(acc[1][2*ntp+1], a1l[0],a1l[1],a1l[2],a1l[3], bc[2],bc[3]);
        }
    }
}

#define ZERO_ACC(acc) \
    _Pragma("unroll") for (int mt = 0; mt < 2; mt++) \
    _Pragma("unroll") for (int nt = 0; nt < 8; nt++) \
    _Pragma("unroll") for (int i = 0; i < 4; i++) acc[mt][nt][i] = 0.f;

// ---------------- fused edge kernel, one CTA per (b,m), 512 threads ---------
// attn is stored SCALED x256 (true_attn = stored/256) so the fp16 lo-term
// stays in normal range. Softmax reads x(1/256); edge epilogue applies 1/256.
__global__ __launch_bounds__(THREADS, 1) void edge_kernel(
    const float* __restrict__ mol_adj, const float* __restrict__ prot_adj,
    const float* __restrict__ bka,  const float* __restrict__ bva,
    const float* __restrict__ boed, const float* __restrict__ bond,
    const float* __restrict__ Wond,
    float* __restrict__ out_node, float* __restrict__ out_edge,
    float* __restrict__ out_prot_adj)
{
    char* sm = smem_raw;
    const uint32_t sbase = smem_to_u32(sm);
    const int tid = threadIdx.x, wid = tid >> 5, lane = tid & 31;
    const int lg = lane >> 2, lt = lane & 3;
    const int bm = blockIdx.x, b = bm >> 7;
    const int R0 = (wid >> 2)*32, C0 = (wid & 3)*64;   // 4x4 warp grid

    float* qs = (float*)(sm + OFF_QS);
    const float* Ap = prot_adj + (size_t)bm*NN*CC;
    const float* Am = mol_adj  + (size_t)bm*NN*CC;
    float* outp = out_prot_adj + (size_t)bm*NN*CC;

    if (tid < 256) qs[tid] = g_q[bm*CC + tid];

    float acc[2][8][4];
    float4 pf[2];

    // prologue
    ldgA(pf, Ap, 0, tid);
    cpB(sbase + OFF_B, g_WkaT, 0, tid);
    __syncthreads();

    // ======== Phase A: prot_e (writes prot passthrough from pf) ========
    ZERO_ACC(acc);
    for (int ch = 0; ch < NCHK; ch++) {
        char* ab = sm + OFF_A + (ch & 1)*ABUF_B;
        uint32_t abu = sbase + OFF_A + (ch & 1)*ABUF_B;
        stsA(ab, pf, tid, outp, ch*CHK);
        if (ch < 7) ldgA(pf, Ap, (ch+1)*CHK, tid);
        else        ldgA(pf, Am, 0, tid);
        CP_WAIT0();
        __syncthreads();
        uint32_t nb = sbase + OFF_B + (((ch & 1) ^ 1))*BBUF_B;
        if (ch < 7) cpB(nb, g_WkaT, (ch+1)*CHK, tid);
        else        cpB(nb, g_WvaT, 0, tid);
        uint32_t bbu = sbase + OFF_B + (ch & 1)*BBUF_B;
        mma_chunk(abu, abu + 8192, bbu, acc, R0, C0, lane);
    }
    // epilogue A: split(pe + bka + 1) into attn hi/lo (fp16)
#pragma unroll
    for (int mt = 0; mt < 2; mt++) {
        int r = R0 + mt*16 + lg;
#pragma unroll
        for (int nt = 0; nt < 8; nt++) {
            int c = C0 + nt*8 + lt*2;
            uint32_t coff = ((uint32_t)(c >> 5))*8192u;
            int wloc = (c & 31) >> 1;
            float b0v = __ldg(bka + c) + 1.0f, b1v = __ldg(bka + c + 1) + 1.0f;
            uint32_t h, l;
            uint32_t o0 = coff + swz(r, wloc), o1 = coff + swz(r + 8, wloc);
            split2h(acc[mt][nt][0] + b0v, acc[mt][nt][1] + b1v, h, l);
            *(uint32_t*)(sm + OFF_ATH + o0) = h;
            *(uint32_t*)(sm + OFF_ATL + o0) = l;
            split2h(acc[mt][nt][2] + b0v, acc[mt][nt][3] + b1v, h, l);
            *(uint32_t*)(sm + OFF_ATH + o1) = h;
            *(uint32_t*)(sm + OFF_ATL + o1) = l;
        }
    }

    // ======== Phase B: mol_e ========
    ZERO_ACC(acc);
    for (int ch = 0; ch < NCHK; ch++) {
        char* ab = sm + OFF_A + (ch & 1)*ABUF_B;
        uint32_t abu = sbase + OFF_A + (ch & 1)*ABUF_B;
        stsA(ab, pf, tid, (float*)0, 0);
        if (ch < 7) ldgA(pf, Am, (ch+1)*CHK, tid);
        CP_WAIT0();
        __syncthreads();
        uint32_t nb = sbase + OFF_B + (((ch & 1) ^ 1))*BBUF_B;
        if (ch < 7) cpB(nb, g_WvaT, (ch+1)*CHK, tid);
        else        cpB(nb, g_WoedT, 0, tid);
        uint32_t bbu = sbase + OFF_B + (ch & 1)*BBUF_B;
        mma_chunk(abu, abu + 8192, bbu, acc, R0, C0, lane);
    }
    // epilogue B: attn_scaled = pe * (me + bva) * (q*16) * k   [= true_attn*256]
    {
        const int bbase = b << 7;
#pragma unroll
        for (int mt = 0; mt < 2; mt++) {
            int r = R0 + mt*16 + lg;
#pragma unroll
            for (int nt = 0; nt < 8; nt++) {
                int c = C0 + nt*8 + lt*2;
                uint32_t coff = ((uint32_t)(c >> 5))*8192u;
                int wloc = (c & 31) >> 1;
                uint32_t o0 = coff + swz(r, wloc), o1 = coff + swz(r + 8, wloc);
                float bv0 = __ldg(bva + c), bv1 = __ldg(bva + c + 1);
                float q0 = qs[c] * 16.0f, q1 = qs[c+1] * 16.0f;
                float k00 = g_kT[c*ROWS_TOT + bbase + r];
                float k01 = g_kT[(c+1)*ROWS_TOT + bbase + r];
                float k10 = g_kT[c*ROWS_TOT + bbase + r + 8];
                float k11 = g_kT[(c+1)*ROWS_TOT + bbase + r + 8];
                uint32_t uh0 = *(uint32_t*)(sm + OFF_ATH + o0);
                uint32_t ul0 = *(uint32_t*)(sm + OFF_ATL + o0);
                uint32_t uh1 = *(uint32_t*)(sm + OFF_ATH + o1);
                uint32_t ul1 = *(uint32_t*)(sm + OFF_ATL + o1);
                float p00 = rec_h(uh0, ul0, 0), p01 = rec_h(uh0, ul0, 1);
                float p10 = rec_h(uh1, ul1, 0), p11 = rec_h(uh1, ul1, 1);
                float a0 = p00 * (acc[mt][nt][0] + bv0) * q0 * k00;
                float a1 = p01 * (acc[mt][nt][1] + bv1) * q1 * k01;
                float a2 = p10 * (acc[mt][nt][2] + bv0) * q0 * k10;
                float a3 = p11 * (acc[mt][nt][3] + bv1) * q1 * k11;
                uint32_t h, l;
                split2h(a0, a1, h, l);
                *(uint32_t*)(sm + OFF_ATH + o0) = h;
                *(uint32_t*)(sm + OFF_ATL + o0) = l;
                split2h(a2, a3, h, l);
                *(uint32_t*)(sm + OFF_ATH + o1) = h;
                *(uint32_t*)(sm + OFF_ATL + o1) = l;
            }
        }
    }

    // ======== Phase C: edge_out = (attn_scaled @ Woed)/256 + boed ========
    ZERO_ACC(acc);
    for (int ch = 0; ch < NCHK; ch++) {
        CP_WAIT0();
        __syncthreads();
        uint32_t nb = sbase + OFF_B + (((ch & 1) ^ 1))*BBUF_B;
        if (ch < 7) cpB(nb, g_WoedT, (ch+1)*CHK, tid);
        uint32_t ah = sbase + OFF_ATH + ch*8192;
        uint32_t al = sbase + OFF_ATL + ch*8192;
        uint32_t bbu = sbase + OFF_B + (ch & 1)*BBUF_B;
        mma_chunk(ah, al, bbu, acc, R0, C0, lane);
    }
    // epilogue C: scale back 1/256 and store
#pragma unroll
    for (int mt = 0; mt < 2; mt++) {
        int r = R0 + mt*16 + lg;
#pragma unroll
        for (int nt = 0; nt < 8; nt++) {
            int c = C0 + nt*8 + lt*2;
            float b0v = __ldg(boed + c), b1v = __ldg(boed + c + 1);
            *(float2*)(out_edge + ((size_t)bm*NN + r)*CC + c) =
                make_float2(acc[mt][nt][0]*0.00390625f + b0v,
                            acc[mt][nt][1]*0.00390625f + b1v);
            *(float2*)(out_edge + ((size_t)bm*NN + r + 8)*CC + c) =
                make_float2(acc[mt][nt][2]*0.00390625f + b0v,
                            acc[mt][nt][3]*0.00390625f + b1v);
        }
    }

    // ======== softmax (2-way split over n) + node projection ========
    {
        float* red  = (float*)(sm + OFF_A);
        float* red2 = (float*)(sm + OFF_A + 2048);
        float* nodes = (float*)(sm + OFF_NODES);

        const int c = tid & 255, half = tid >> 8;
        const int odd = c & 1;
        const int wloc = (c & 31) >> 1;
        const char* bh = sm + OFF_ATH + ((uint32_t)(c >> 5))*8192u;
        const char* bl = sm + OFF_ATL + ((uint32_t)(c >> 5))*8192u;
        const int n0 = half*64;

        float mx = -1e30f;
#pragma unroll 4
        for (int i = 0; i < 64; i++) {
            uint32_t off = swz(n0 + i, wloc);
            float v = rec_h(*(const uint32_t*)(bh + off),
                            *(const uint32_t*)(bl + off), odd);
            mx = fmaxf(mx, v);
        }
        red[tid] = mx;
        __syncthreads();
        mx = fmaxf(red[c], red[256 + c]);

        float s = 0.f, nv = 0.f;
        const float* vb = g_v + (size_t)((b << 7) + n0)*CC + c;
#pragma unroll 4
        for (int i = 0; i < 64; i++) {
            uint32_t off = swz(n0 + i, wloc);
            float v = rec_h(*(const uint32_t*)(bh + off),
                            *(const uint32_t*)(bl + off), odd);
            float e = __expf((v - mx) * 0.00390625f);
            s += e;
            nv += e * vb[(size_t)i*CC];
        }
        __syncthreads();
        red[tid] = s; red2[tid] = nv;
        __syncthreads();
        if (tid < 256)
            nodes[c] = (red2[c] + red2[256 + c]) / (red[c] + red[256 + c]);
        __syncthreads();

        float a2 = 0.f;
        const int k0 = half*128;
#pragma unroll 4
        for (int k = 0; k < 128; k++)
            a2 += nodes[k0 + k] * Wond[(k0 + k)*CC + c];
        red[tid] = a2;
        __syncthreads();
        if (tid < 256)
            out_node[bm*CC + c] = red[c] + red[256 + c] + __ldg(bond + c);
    }
}

// ---------------- launch ----------------
extern "C" void kernel_launch(void* const* d_in, const int* in_sizes, int n_in,
                              void* d_out, int out_size)
{
    const float* mol_annot  = (const float*)d_in[0];
    const float* prot_annot = (const float*)d_in[1];
    const float* mol_adj    = (const float*)d_in[2];
    const float* prot_adj   = (const float*)d_in[3];
    const float* Wq   = (const float*)d_in[4];   const float* bq   = (const float*)d_in[5];
    const float* Wk   = (const float*)d_in[6];   const float* bk   = (const float*)d_in[7];
    const float* Wv   = (const float*)d_in[8];   const float* bv   = (const float*)d_in[9];
    const float* Wka  = (const float*)d_in[10];  const float* bka  = (const float*)d_in[11];
    const float* Wva  = (const float*)d_in[12];  const float* bva  = (const float*)d_in[13];
    const float* Wond = (const float*)d_in[14];  const float* bond = (const float*)d_in[15];
    const float* Woed = (const float*)d_in[16];  const float* boed = (const float*)d_in[17];

    float* out = (float*)d_out;
    const size_t ANNOT = (size_t)BB*NN*CC;
    const size_t ADJ   = (size_t)BB*NN*NN*CC;
    float* out_node       = out;
    float* out_prot_annot = out + ANNOT;
    float* out_edge       = out + 2*ANNOT;
    float* out_prot_adj   = out + 2*ANNOT + ADJ;

    cudaFuncSetAttribute(edge_kernel,
                         cudaFuncAttributeMaxDynamicSharedMemorySize, SMEM_BYTES);

    prep_kernel<<<120, 256>>>(Wka, Wva, Woed,
                              mol_annot, prot_annot, Wq, bq, Wk, bk, Wv, bv,
                              out_prot_annot);

    edge_kernel<<<ROWS_TOT, THREADS, SMEM_BYTES>>>(
        mol_adj, prot_adj, bka, bva, boed, bond, Wond,
        out_node, out_edge, out_prot_adj);
}